// round 5
// baseline (speedup 1.0000x reference)
#include <cuda_runtime.h>
#include <math.h>

// Problem constants
#define BB 2
#define TT 2048
#define CC 1024
#define NH 16
#define HD 64
#define WINDOW 256
#define SINK 4
#define MROWS (BB*TT)          // 4096
#define C3 (3*CC)              // 3072

// Scratch (device globals: no allocation allowed)
__device__ float g_qkv[MROWS * C3];   // [B*T, 3C]  (q | k | v)
__device__ float g_att[MROWS * CC];   // attention output before proj

// ---------------------------------------------------------------------------
// SGEMM: C[M,N] = A[M,K] @ B[K,N], all row-major, fp32.
// 128x128 tile, BK=16, 256 threads, 8x8 micro-tile.
// ---------------------------------------------------------------------------
__global__ __launch_bounds__(256, 2)
void sgemm_kernel(const float* __restrict__ A, const float* __restrict__ Bm,
                  float* __restrict__ Cm, int M, int N, int K)
{
    __shared__ float As[16][128];   // As[k][m]
    __shared__ float Bs[16][128];   // Bs[k][n]
    const int tid = threadIdx.x;
    const int bm = blockIdx.y * 128;
    const int bn = blockIdx.x * 128;
    const int tm = (tid >> 4) * 8;
    const int tn = (tid & 15) * 8;

    float acc[8][8];
#pragma unroll
    for (int i = 0; i < 8; i++)
#pragma unroll
        for (int j = 0; j < 8; j++) acc[i][j] = 0.f;

    for (int k0 = 0; k0 < K; k0 += 16) {
#pragma unroll
        for (int l = 0; l < 2; l++) {
            int gid = tid + l * 256;           // 0..511
            int row = gid >> 2;                // 0..127
            int c4  = (gid & 3) << 2;          // 0,4,8,12
            float4 v = *reinterpret_cast<const float4*>(&A[(size_t)(bm + row) * K + k0 + c4]);
            As[c4 + 0][row] = v.x;
            As[c4 + 1][row] = v.y;
            As[c4 + 2][row] = v.z;
            As[c4 + 3][row] = v.w;
        }
#pragma unroll
        for (int l = 0; l < 2; l++) {
            int gid = tid + l * 256;
            int row = gid >> 5;                // 0..15
            int c4  = (gid & 31) << 2;         // 0..124
            float4 v = *reinterpret_cast<const float4*>(&Bm[(size_t)(k0 + row) * N + bn + c4]);
            *reinterpret_cast<float4*>(&Bs[row][c4]) = v;
        }
        __syncthreads();
#pragma unroll
        for (int kk = 0; kk < 16; kk++) {
            float ar[8], br[8];
            float4 a0 = *reinterpret_cast<const float4*>(&As[kk][tm]);
            float4 a1 = *reinterpret_cast<const float4*>(&As[kk][tm + 4]);
            float4 b0 = *reinterpret_cast<const float4*>(&Bs[kk][tn]);
            float4 b1 = *reinterpret_cast<const float4*>(&Bs[kk][tn + 4]);
            ar[0]=a0.x; ar[1]=a0.y; ar[2]=a0.z; ar[3]=a0.w;
            ar[4]=a1.x; ar[5]=a1.y; ar[6]=a1.z; ar[7]=a1.w;
            br[0]=b0.x; br[1]=b0.y; br[2]=b0.z; br[3]=b0.w;
            br[4]=b1.x; br[5]=b1.y; br[6]=b1.z; br[7]=b1.w;
#pragma unroll
            for (int i = 0; i < 8; i++)
#pragma unroll
                for (int j = 0; j < 8; j++)
                    acc[i][j] += ar[i] * br[j];
        }
        __syncthreads();
    }
#pragma unroll
    for (int i = 0; i < 8; i++) {
#pragma unroll
        for (int j = 0; j < 8; j += 4) {
            float4 v = make_float4(acc[i][j], acc[i][j+1], acc[i][j+2], acc[i][j+3]);
            *reinterpret_cast<float4*>(&Cm[(size_t)(bm + tm + i) * N + bn + tn + j]) = v;
        }
    }
}

// ---------------------------------------------------------------------------
// RoPE in place on q and k slices of g_qkv.
// One thread per (b,t,h,d2), d2 in [0,32): handles dims d2 and d2+32.
// ---------------------------------------------------------------------------
__global__ __launch_bounds__(256)
void rope_kernel(float* __restrict__ qkv)
{
    int idx = blockIdx.x * blockDim.x + threadIdx.x;   // 0 .. B*T*NH*32-1
    int d2 = idx & 31;
    int h  = (idx >> 5) & (NH - 1);
    int t  = (idx >> 9) & (TT - 1);
    int b  = idx >> 20;
    if (b >= BB) return;

    // match reference eval order: 1 / (10000 ** (d2/32)), angle in fp32,
    // then high-precision sin/cos of that fp32 angle
    float invf = 1.0f / powf(10000.0f, (float)d2 / 32.0f);
    float ang  = (float)t * invf;
    float c = (float)cos((double)ang);
    float s = (float)sin((double)ang);

    size_t base = (size_t)(b * TT + t) * C3 + h * HD;
#pragma unroll
    for (int part = 0; part < 2; part++) {      // 0 = q, 1 = k
        float* p = qkv + base + part * CC;
        float a0 = p[d2];
        float a1 = p[d2 + 32];
        p[d2]      = a0 * c - a1 * s;
        p[d2 + 32] = a1 * c + a0 * s;
    }
}

// ---------------------------------------------------------------------------
// Windowed causal attention with sink tokens. STATIC shared memory (<48KB).
// One block = (b, h, 64-query tile). Key chunks of 32 rows: only the <=11
// relevant chunks (sink chunk 0 + window chunks) are touched. Online softmax.
// Thread layout: sq = tid/4 (query row 0..63), kt = tid%4
//   scoring: thread handles 8 keys kt*8..kt*8+7 for query sq
//   PV:      thread handles 16 dims kt*16..kt*16+15 for query sq
// ---------------------------------------------------------------------------
#define CHUNK 32
#define PS_STRIDE 33

__global__ __launch_bounds__(256)
void attn_kernel(const float* __restrict__ qkv, float* __restrict__ att)
{
    __shared__ float Qs[64 * 64];           // 16 KB (scaled q)
    __shared__ float Ks[CHUNK * 64];        //  8 KB
    __shared__ float Vs[CHUNK * 64];        //  8 KB
    __shared__ float Ps[64 * PS_STRIDE];    //  8.25 KB

    const int tid = threadIdx.x;
    const int bid = blockIdx.x;       // b*NH*32 + h*32 + qb
    const int qb = bid & 31;
    const int h  = (bid >> 5) & (NH - 1);
    const int b  = bid >> 9;
    const int q0 = qb * 64;
    const int sq = tid >> 2;
    const int kt = tid & 3;
    const float scale = 0.125f;       // 1/sqrt(64)

    // Load Q tile (scaled): 1024 float4, 4 per thread
#pragma unroll
    for (int i = 0; i < 4; i++) {
        int f = tid + i * 256;
        int r = f >> 4;
        int c4 = (f & 15) << 2;
        float4 v = *reinterpret_cast<const float4*>(
            &qkv[(size_t)(b * TT + q0 + r) * C3 + h * HD + c4]);
        v.x *= scale; v.y *= scale; v.z *= scale; v.w *= scale;
        *reinterpret_cast<float4*>(&Qs[r * 64 + c4]) = v;
    }

    float m = -1e30f, l = 0.f;
    float o[16];
#pragma unroll
    for (int i = 0; i < 16; i++) o[i] = 0.f;

    const int cstart = (q0 - WINDOW > 0) ? (q0 - WINDOW) : 0;
    const int do_sink = (cstart > 0) ? 1 : 0;
    const int nwin = (q0 + 64 - cstart) / CHUNK;  // chunks cstart .. q0+32
    const int nch = nwin + do_sink;

    for (int phase = 0; phase < nch; phase++) {
        const int c = (do_sink && phase == 0) ? 0 : cstart + (phase - do_sink) * CHUNK;

        __syncthreads();   // protect Ks/Vs/Ps (and Qs on phase 0) reuse
        // load K and V chunks: 512 float4 each, 2 per thread each
#pragma unroll
        for (int i = 0; i < 2; i++) {
            int f = tid + i * 256;
            int r = f >> 4;
            int c4 = (f & 15) << 2;
            size_t rowbase = (size_t)(b * TT + c + r) * C3 + h * HD + c4;
            *reinterpret_cast<float4*>(&Ks[r * 64 + c4]) =
                *reinterpret_cast<const float4*>(&qkv[rowbase + CC]);
            *reinterpret_cast<float4*>(&Vs[r * 64 + c4]) =
                *reinterpret_cast<const float4*>(&qkv[rowbase + 2 * CC]);
        }
        __syncthreads();

        // ---- scores: 8 keys for query sq ----
        float s[8];
#pragma unroll
        for (int i = 0; i < 8; i++) s[i] = 0.f;
#pragma unroll
        for (int d4 = 0; d4 < 16; d4++) {
            float4 qv = *reinterpret_cast<const float4*>(&Qs[sq * 64 + d4 * 4]);
#pragma unroll
            for (int kki = 0; kki < 8; kki++) {
                float4 kv = *reinterpret_cast<const float4*>(&Ks[(kt * 8 + kki) * 64 + d4 * 4]);
                s[kki] += qv.x * kv.x + qv.y * kv.y + qv.z * kv.z + qv.w * kv.w;
            }
        }
        const int q = q0 + sq;
        float mc = -1e30f;
#pragma unroll
        for (int kki = 0; kki < 8; kki++) {
            int j = c + kt * 8 + kki;
            bool allowed = (j <= q) && (((q - j) < WINDOW) || (j < SINK));
            if (!allowed) s[kki] = -1e30f;
            mc = fmaxf(mc, s[kki]);
        }
        // reduce max across the 4 threads of this query row (aligned lane group)
        mc = fmaxf(mc, __shfl_xor_sync(0xffffffffu, mc, 1));
        mc = fmaxf(mc, __shfl_xor_sync(0xffffffffu, mc, 2));
        float mn = fmaxf(m, mc);
        float alpha = expf(m - mn);

        float lc = 0.f;
#pragma unroll
        for (int kki = 0; kki < 8; kki++) {
            float p = expf(s[kki] - mn);
            lc += p;
            Ps[sq * PS_STRIDE + kt * 8 + kki] = p;
        }
        lc += __shfl_xor_sync(0xffffffffu, lc, 1);
        lc += __shfl_xor_sync(0xffffffffu, lc, 2);
        l = l * alpha + lc;
        m = mn;

        __syncthreads();   // all P written before PV

        // ---- PV: 16 dims for query sq ----
#pragma unroll
        for (int i = 0; i < 16; i++) o[i] *= alpha;
        for (int j = 0; j < CHUNK; j++) {
            float p = Ps[sq * PS_STRIDE + j];
#pragma unroll
            for (int i4 = 0; i4 < 4; i4++) {
                float4 v = *reinterpret_cast<const float4*>(&Vs[j * 64 + kt * 16 + i4 * 4]);
                o[i4 * 4 + 0] += p * v.x;
                o[i4 * 4 + 1] += p * v.y;
                o[i4 * 4 + 2] += p * v.z;
                o[i4 * 4 + 3] += p * v.w;
            }
        }
    }

    float inv = 1.0f / l;
    size_t obase = (size_t)(b * TT + q0 + sq) * CC + h * HD + kt * 16;
#pragma unroll
    for (int i4 = 0; i4 < 4; i4++) {
        float4 v = make_float4(o[i4*4]*inv, o[i4*4+1]*inv, o[i4*4+2]*inv, o[i4*4+3]*inv);
        *reinterpret_cast<float4*>(&att[obase + i4 * 4]) = v;
    }
}

// ---------------------------------------------------------------------------
extern "C" void kernel_launch(void* const* d_in, const int* in_sizes, int n_in,
                              void* d_out, int out_size)
{
    // Bind inputs by element count (robust to metadata ordering):
    //   x: B*T*C = 4,194,304   w_attn: C*3C = 3,145,728   w_proj: C*C = 1,048,576
    const float* x = nullptr;
    const float* w_attn = nullptr;
    const float* w_proj = nullptr;
    for (int i = 0; i < n_in; i++) {
        if (in_sizes[i] == BB * TT * CC)      x      = (const float*)d_in[i];
        else if (in_sizes[i] == CC * C3)      w_attn = (const float*)d_in[i];
        else if (in_sizes[i] == CC * CC)      w_proj = (const float*)d_in[i];
    }
    // Fallback: reference signature order (x, w_attn, w_proj)
    if (!x || !w_attn || !w_proj) {
        x      = (const float*)d_in[0];
        w_attn = (const float*)d_in[1];
        w_proj = (const float*)d_in[2];
    }
    float* out = (float*)d_out;

    void* p_qkv = nullptr;
    void* p_att = nullptr;
    cudaGetSymbolAddress(&p_qkv, g_qkv);
    cudaGetSymbolAddress(&p_att, g_att);
    float* qkv = (float*)p_qkv;
    float* att = (float*)p_att;

    // 1) qkv = x @ w_attn    [4096,1024] @ [1024,3072]
    {
        dim3 grid(C3 / 128, MROWS / 128);
        sgemm_kernel<<<grid, 256>>>(x, w_attn, qkv, MROWS, C3, CC);
    }
    // 2) RoPE on q,k
    {
        int total = BB * TT * NH * 32;
        rope_kernel<<<total / 256, 256>>>(qkv);
    }
    // 3) windowed attention (static smem, no attribute needed)
    {
        int grid = BB * NH * (TT / 64);
        attn_kernel<<<grid, 256>>>(qkv, att);
    }
    // 4) out = att @ w_proj  [4096,1024] @ [1024,1024]
    {
        dim3 grid(CC / 128, MROWS / 128);
        sgemm_kernel<<<grid, 256>>>(att, w_proj, out, MROWS, CC, CC);
    }
}

// round 9
// speedup vs baseline: 1.9663x; 1.9663x over previous
#include <cuda_runtime.h>
#include <cuda_bf16.h>
#include <mma.h>
#include <math.h>

using namespace nvcuda;

// Problem constants
#define BB 2
#define TT 2048
#define CC 1024
#define NH 16
#define HD 64
#define WINDOW 256
#define SINK 4
#define MROWS (BB*TT)
#define C3 (3*CC)

// Scratch (device globals: no allocation allowed)
__device__ float g_qkv[MROWS * C3];
__device__ float g_att[MROWS * CC];

// ===========================================================================
// Tensor-core GEMM (split-bf16 3-pass) via WMMA: C = A @ B, fp32 io.
// a = ah + al, b = bh + bl (bf16 hi/lo); acc += ah*bh + ah*bl + al*bh.
// Block 128x128, BK=32, 256 threads = 8 warps; warp tile 32x64 (2x4 frags).
// ===========================================================================
#define ASTRIDE 40
#define BSTRIDE 136

__device__ __forceinline__ void split2(float x, __nv_bfloat16& h, __nv_bfloat16& l) {
    __nv_bfloat16 hb = __float2bfloat16(x);
    float r = x - __bfloat162float(hb);
    h = hb;
    l = __float2bfloat16(r);
}

__global__ __launch_bounds__(256)
void gemm_tc_kernel(const float* __restrict__ A, const float* __restrict__ Bm,
                    float* __restrict__ Cm, int M, int N, int K)
{
    __shared__ __nv_bfloat16 Ah[128 * ASTRIDE];
    __shared__ __nv_bfloat16 Al[128 * ASTRIDE];
    __shared__ __nv_bfloat16 Bh[32 * BSTRIDE];
    __shared__ __nv_bfloat16 Bl[32 * BSTRIDE];

    const int tid  = threadIdx.x;
    const int warp = tid >> 5;
    const int wm = warp & 3;
    const int wn = warp >> 2;
    const int bm = blockIdx.y * 128;
    const int bn = blockIdx.x * 128;

    wmma::fragment<wmma::accumulator, 16, 16, 16, float> acc[2][4];
#pragma unroll
    for (int mt = 0; mt < 2; mt++) {
#pragma unroll
        for (int nt = 0; nt < 4; nt++) {
            wmma::fill_fragment(acc[mt][nt], 0.0f);
        }
    }

    for (int k0 = 0; k0 < K; k0 += 32) {
        // load + split A tile: 128 rows x 32 cols
#pragma unroll
        for (int i = 0; i < 4; i++) {
            int gid = tid + i * 256;
            int row = gid >> 3;
            int c4  = (gid & 7) << 2;
            float4 v = *reinterpret_cast<const float4*>(&A[(size_t)(bm + row) * K + k0 + c4]);
            int base = row * ASTRIDE + c4;
            __nv_bfloat16 h0, l0;
            split2(v.x, h0, l0);
            Ah[base + 0] = h0;
            Al[base + 0] = l0;
            split2(v.y, h0, l0);
            Ah[base + 1] = h0;
            Al[base + 1] = l0;
            split2(v.z, h0, l0);
            Ah[base + 2] = h0;
            Al[base + 2] = l0;
            split2(v.w, h0, l0);
            Ah[base + 3] = h0;
            Al[base + 3] = l0;
        }
        // load + split B tile: 32 rows x 128 cols
#pragma unroll
        for (int i = 0; i < 4; i++) {
            int gid = tid + i * 256;
            int row = gid >> 5;
            int c4  = (gid & 31) << 2;
            float4 v = *reinterpret_cast<const float4*>(&Bm[(size_t)(k0 + row) * N + bn + c4]);
            int base = row * BSTRIDE + c4;
            __nv_bfloat16 h0, l0;
            split2(v.x, h0, l0);
            Bh[base + 0] = h0;
            Bl[base + 0] = l0;
            split2(v.y, h0, l0);
            Bh[base + 1] = h0;
            Bl[base + 1] = l0;
            split2(v.z, h0, l0);
            Bh[base + 2] = h0;
            Bl[base + 2] = l0;
            split2(v.w, h0, l0);
            Bh[base + 3] = h0;
            Bl[base + 3] = l0;
        }
        __syncthreads();

#pragma unroll
        for (int ks = 0; ks < 2; ks++) {
            wmma::fragment<wmma::matrix_a, 16, 16, 16, __nv_bfloat16, wmma::row_major> fa_h[2];
            wmma::fragment<wmma::matrix_a, 16, 16, 16, __nv_bfloat16, wmma::row_major> fa_l[2];
            wmma::fragment<wmma::matrix_b, 16, 16, 16, __nv_bfloat16, wmma::row_major> fb_h[4];
            wmma::fragment<wmma::matrix_b, 16, 16, 16, __nv_bfloat16, wmma::row_major> fb_l[4];
#pragma unroll
            for (int mt = 0; mt < 2; mt++) {
                const __nv_bfloat16* pa = &Ah[(wm * 32 + mt * 16) * ASTRIDE + ks * 16];
                wmma::load_matrix_sync(fa_h[mt], pa, ASTRIDE);
                const __nv_bfloat16* pl = &Al[(wm * 32 + mt * 16) * ASTRIDE + ks * 16];
                wmma::load_matrix_sync(fa_l[mt], pl, ASTRIDE);
            }
#pragma unroll
            for (int nt = 0; nt < 4; nt++) {
                const __nv_bfloat16* pb = &Bh[(ks * 16) * BSTRIDE + wn * 64 + nt * 16];
                wmma::load_matrix_sync(fb_h[nt], pb, BSTRIDE);
                const __nv_bfloat16* pl = &Bl[(ks * 16) * BSTRIDE + wn * 64 + nt * 16];
                wmma::load_matrix_sync(fb_l[nt], pl, BSTRIDE);
            }
#pragma unroll
            for (int mt = 0; mt < 2; mt++) {
#pragma unroll
                for (int nt = 0; nt < 4; nt++) {
                    wmma::mma_sync(acc[mt][nt], fa_h[mt], fb_h[nt], acc[mt][nt]);
                    wmma::mma_sync(acc[mt][nt], fa_h[mt], fb_l[nt], acc[mt][nt]);
                    wmma::mma_sync(acc[mt][nt], fa_l[mt], fb_h[nt], acc[mt][nt]);
                }
            }
        }
        __syncthreads();
    }

    // epilogue: store fragments directly to global
#pragma unroll
    for (int mt = 0; mt < 2; mt++) {
        int row0 = bm + wm * 32 + mt * 16;
#pragma unroll
        for (int nt = 0; nt < 4; nt++) {
            int col0 = bn + wn * 64 + nt * 16;
            float* dst = &Cm[(size_t)row0 * N + col0];
            wmma::store_matrix_sync(dst, acc[mt][nt], N, wmma::mem_row_major);
        }
    }
}

// ---------------------------------------------------------------------------
// RoPE in place on q and k slices of g_qkv.
// ---------------------------------------------------------------------------
__global__ __launch_bounds__(256)
void rope_kernel(float* __restrict__ qkv)
{
    int idx = blockIdx.x * blockDim.x + threadIdx.x;
    int d2 = idx & 31;
    int h  = (idx >> 5) & (NH - 1);
    int t  = (idx >> 9) & (TT - 1);
    int b  = idx >> 20;
    if (b >= BB) return;

    float invf = 1.0f / powf(10000.0f, (float)d2 / 32.0f);
    float ang  = (float)t * invf;
    float c = (float)cos((double)ang);
    float s = (float)sin((double)ang);

    size_t base = (size_t)(b * TT + t) * C3 + h * HD;
#pragma unroll
    for (int part = 0; part < 2; part++) {
        float* p = qkv + base + part * CC;
        float a0 = p[d2];
        float a1 = p[d2 + 32];
        p[d2]      = a0 * c - a1 * s;
        p[d2 + 32] = a1 * c + a0 * s;
    }
}

// ---------------------------------------------------------------------------
// Windowed causal attention with sinks. Conflict-free smem layout:
//   Q/K/V row stride 68 floats, Ps stride 36, interleaved key/dim ownership.
// ---------------------------------------------------------------------------
#define CHUNK 32
#define QKV_STRIDE 68
#define PS_STRIDE 36

__global__ __launch_bounds__(256)
void attn_kernel(const float* __restrict__ qkv, float* __restrict__ att)
{
    __shared__ float Qs[64 * QKV_STRIDE];
    __shared__ float Ks[CHUNK * QKV_STRIDE];
    __shared__ float Vs[CHUNK * QKV_STRIDE];
    __shared__ float Ps[64 * PS_STRIDE];

    const int tid = threadIdx.x;
    const int bid = blockIdx.x;
    const int qb = bid & 31;
    const int h  = (bid >> 5) & (NH - 1);
    const int b  = bid >> 9;
    const int q0 = qb * 64;
    const int sq = tid >> 2;
    const int kt = tid & 3;
    const float scale = 0.125f;

#pragma unroll
    for (int i = 0; i < 4; i++) {
        int f = tid + i * 256;
        int r = f >> 4;
        int c4 = (f & 15) << 2;
        const float* src = &qkv[(size_t)(b * TT + q0 + r) * C3 + h * HD + c4];
        float4 v = *reinterpret_cast<const float4*>(src);
        v.x *= scale;
        v.y *= scale;
        v.z *= scale;
        v.w *= scale;
        *reinterpret_cast<float4*>(&Qs[r * QKV_STRIDE + c4]) = v;
    }

    float m = -1e30f;
    float l = 0.f;
    float o[16];
#pragma unroll
    for (int i = 0; i < 16; i++) o[i] = 0.f;

    const int cstart = (q0 - WINDOW > 0) ? (q0 - WINDOW) : 0;
    const int do_sink = (cstart > 0) ? 1 : 0;
    const int nwin = (q0 + 64 - cstart) / CHUNK;
    const int nch = nwin + do_sink;

    for (int phase = 0; phase < nch; phase++) {
        const int c = (do_sink && phase == 0) ? 0 : cstart + (phase - do_sink) * CHUNK;

        __syncthreads();
#pragma unroll
        for (int i = 0; i < 2; i++) {
            int f = tid + i * 256;
            int r = f >> 4;
            int c4 = (f & 15) << 2;
            size_t rowbase = (size_t)(b * TT + c + r) * C3 + h * HD + c4;
            const float* srck = &qkv[rowbase + CC];
            *reinterpret_cast<float4*>(&Ks[r * QKV_STRIDE + c4]) =
                *reinterpret_cast<const float4*>(srck);
            const float* srcv = &qkv[rowbase + 2 * CC];
            *reinterpret_cast<float4*>(&Vs[r * QKV_STRIDE + c4]) =
                *reinterpret_cast<const float4*>(srcv);
        }
        __syncthreads();

        float s[8];
#pragma unroll
        for (int i = 0; i < 8; i++) s[i] = 0.f;
#pragma unroll
        for (int d4 = 0; d4 < 16; d4++) {
            float4 qv = *reinterpret_cast<const float4*>(&Qs[sq * QKV_STRIDE + d4 * 4]);
#pragma unroll
            for (int kki = 0; kki < 8; kki++) {
                const float* kp = &Ks[(kt + kki * 4) * QKV_STRIDE + d4 * 4];
                float4 kv = *reinterpret_cast<const float4*>(kp);
                s[kki] += qv.x * kv.x + qv.y * kv.y + qv.z * kv.z + qv.w * kv.w;
            }
        }
        const int q = q0 + sq;
        float mc = -1e30f;
#pragma unroll
        for (int kki = 0; kki < 8; kki++) {
            int j = c + kt + kki * 4;
            bool allowed = (j <= q) && (((q - j) < WINDOW) || (j < SINK));
            if (!allowed) s[kki] = -1e30f;
            mc = fmaxf(mc, s[kki]);
        }
        mc = fmaxf(mc, __shfl_xor_sync(0xffffffffu, mc, 1));
        mc = fmaxf(mc, __shfl_xor_sync(0xffffffffu, mc, 2));
        float mn = fmaxf(m, mc);
        float alpha = expf(m - mn);

        float lc = 0.f;
#pragma unroll
        for (int kki = 0; kki < 8; kki++) {
            float p = expf(s[kki] - mn);
            lc += p;
            Ps[sq * PS_STRIDE + kt + kki * 4] = p;
        }
        lc += __shfl_xor_sync(0xffffffffu, lc, 1);
        lc += __shfl_xor_sync(0xffffffffu, lc, 2);
        l = l * alpha + lc;
        m = mn;

        __syncthreads();

#pragma unroll
        for (int i = 0; i < 16; i++) o[i] *= alpha;
        for (int j = 0; j < CHUNK; j++) {
            float p = Ps[sq * PS_STRIDE + j];
#pragma unroll
            for (int i4 = 0; i4 < 4; i4++) {
                const float* vp = &Vs[j * QKV_STRIDE + kt * 4 + i4 * 16];
                float4 v = *reinterpret_cast<const float4*>(vp);
                o[i4 * 4 + 0] += p * v.x;
                o[i4 * 4 + 1] += p * v.y;
                o[i4 * 4 + 2] += p * v.z;
                o[i4 * 4 + 3] += p * v.w;
            }
        }
    }

    float inv = 1.0f / l;
    size_t obase = (size_t)(b * TT + q0 + sq) * CC + h * HD + kt * 4;
#pragma unroll
    for (int i4 = 0; i4 < 4; i4++) {
        float4 v = make_float4(o[i4 * 4] * inv, o[i4 * 4 + 1] * inv,
                               o[i4 * 4 + 2] * inv, o[i4 * 4 + 3] * inv);
        *reinterpret_cast<float4*>(&att[obase + i4 * 16]) = v;
    }
}

// ---------------------------------------------------------------------------
extern "C" void kernel_launch(void* const* d_in, const int* in_sizes, int n_in,
                              void* d_out, int out_size)
{
    const float* x = nullptr;
    const float* w_attn = nullptr;
    const float* w_proj = nullptr;
    for (int i = 0; i < n_in; i++) {
        if (in_sizes[i] == BB * TT * CC)      x      = (const float*)d_in[i];
        else if (in_sizes[i] == CC * C3)      w_attn = (const float*)d_in[i];
        else if (in_sizes[i] == CC * CC)      w_proj = (const float*)d_in[i];
    }
    if (!x || !w_attn || !w_proj) {
        x      = (const float*)d_in[0];
        w_attn = (const float*)d_in[1];
        w_proj = (const float*)d_in[2];
    }
    float* out = (float*)d_out;

    void* p_qkv = nullptr;
    void* p_att = nullptr;
    cudaGetSymbolAddress(&p_qkv, g_qkv);
    cudaGetSymbolAddress(&p_att, g_att);
    float* qkv = (float*)p_qkv;
    float* att = (float*)p_att;

    {
        dim3 grid(C3 / 128, MROWS / 128);
        gemm_tc_kernel<<<grid, 256>>>(x, w_attn, qkv, MROWS, C3, CC);
    }
    {
        int total = BB * TT * NH * 32;
        rope_kernel<<<total / 256, 256>>>(qkv);
    }
    {
        int grid = BB * NH * (TT / 64);
        attn_kernel<<<grid, 256>>>(qkv, att);
    }
    {
        dim3 grid(CC / 128, MROWS / 128);
        gemm_tc_kernel<<<grid, 256>>>(att, w_proj, out, MROWS, CC, CC);
    }
}

// round 10
// speedup vs baseline: 2.3183x; 1.1790x over previous
#include <cuda_runtime.h>
#include <cuda_bf16.h>
#include <cuda_pipeline.h>
#include <mma.h>
#include <math.h>

using namespace nvcuda;

// Problem constants
#define BB 2
#define TT 2048
#define CC 1024
#define NH 16
#define HD 64
#define WINDOW 256
#define SINK 4
#define MROWS (BB*TT)
#define C3 (3*CC)

// Scratch (device globals: no allocation allowed)
__device__ float g_qkv[MROWS * C3];
__device__ float g_att[MROWS * CC];
__device__ __nv_bfloat16 g_xh[MROWS * CC];
__device__ __nv_bfloat16 g_xl[MROWS * CC];
__device__ __nv_bfloat16 g_wah[CC * C3];
__device__ __nv_bfloat16 g_wal[CC * C3];
__device__ __nv_bfloat16 g_wph[CC * CC];
__device__ __nv_bfloat16 g_wpl[CC * CC];
__device__ __nv_bfloat16 g_ath[MROWS * CC];
__device__ __nv_bfloat16 g_atl[MROWS * CC];

// ---------------------------------------------------------------------------
// Split fp32 -> bf16 hi + bf16 lo (residual). Vectorized float4 per thread.
// ---------------------------------------------------------------------------
__global__ __launch_bounds__(256)
void split_kernel(const float* __restrict__ src,
                  __nv_bfloat16* __restrict__ dh,
                  __nv_bfloat16* __restrict__ dl, int n4)
{
    int idx = blockIdx.x * blockDim.x + threadIdx.x;
    if (idx >= n4) return;
    float4 v = reinterpret_cast<const float4*>(src)[idx];
    float vals[4];
    vals[0] = v.x;
    vals[1] = v.y;
    vals[2] = v.z;
    vals[3] = v.w;
    unsigned short hs[4];
    unsigned short ls[4];
#pragma unroll
    for (int i = 0; i < 4; i++) {
        __nv_bfloat16 hb = __float2bfloat16(vals[i]);
        float r = vals[i] - __bfloat162float(hb);
        __nv_bfloat16 lb = __float2bfloat16(r);
        hs[i] = __bfloat16_as_ushort(hb);
        ls[i] = __bfloat16_as_ushort(lb);
    }
    uint2 hp;
    hp.x = (uint32_t)hs[0] | ((uint32_t)hs[1] << 16);
    hp.y = (uint32_t)hs[2] | ((uint32_t)hs[3] << 16);
    uint2 lp;
    lp.x = (uint32_t)ls[0] | ((uint32_t)ls[1] << 16);
    lp.y = (uint32_t)ls[2] | ((uint32_t)ls[3] << 16);
    reinterpret_cast<uint2*>(dh)[idx] = hp;
    reinterpret_cast<uint2*>(dl)[idx] = lp;
}

// ===========================================================================
// Double-buffered split-bf16 GEMM: C = (Ah+Al) @ (Bh+Bl) (3-pass), fp32 acc.
// Block 128x128, BK=16, 8 warps (warp tile 32x64), cp.async 2-stage pipeline.
// ===========================================================================
#define ASTRIDE 24
#define BSTRIDE 136

__global__ __launch_bounds__(256)
void gemm_tc_kernel(const __nv_bfloat16* __restrict__ Ahg,
                    const __nv_bfloat16* __restrict__ Alg,
                    const __nv_bfloat16* __restrict__ Bhg,
                    const __nv_bfloat16* __restrict__ Blg,
                    float* __restrict__ Cm, int M, int N, int K)
{
    __shared__ __nv_bfloat16 sAh[2][128 * ASTRIDE];
    __shared__ __nv_bfloat16 sAl[2][128 * ASTRIDE];
    __shared__ __nv_bfloat16 sBh[2][16 * BSTRIDE];
    __shared__ __nv_bfloat16 sBl[2][16 * BSTRIDE];

    const int tid  = threadIdx.x;
    const int warp = tid >> 5;
    const int wm = warp & 3;
    const int wn = warp >> 2;
    const int bm = blockIdx.y * 128;
    const int bn = blockIdx.x * 128;

    // per-thread load mapping
    const int arow = tid >> 1;            // 0..127
    const int acol = (tid & 1) << 3;      // 0 or 8 (bf16 elems)
    const int brow = tid >> 4;            // 0..15
    const int bcol = (tid & 15) << 3;     // 0..120

    wmma::fragment<wmma::accumulator, 16, 16, 16, float> acc[2][4];
#pragma unroll
    for (int mt = 0; mt < 2; mt++) {
#pragma unroll
        for (int nt = 0; nt < 4; nt++) {
            wmma::fill_fragment(acc[mt][nt], 0.0f);
        }
    }

    const int nk = K >> 4;

    // prologue: issue stage 0
    {
        const int k0 = 0;
        __pipeline_memcpy_async(&sAh[0][arow * ASTRIDE + acol],
                                &Ahg[(size_t)(bm + arow) * K + k0 + acol], 16);
        __pipeline_memcpy_async(&sAl[0][arow * ASTRIDE + acol],
                                &Alg[(size_t)(bm + arow) * K + k0 + acol], 16);
        __pipeline_memcpy_async(&sBh[0][brow * BSTRIDE + bcol],
                                &Bhg[(size_t)(k0 + brow) * N + bn + bcol], 16);
        __pipeline_memcpy_async(&sBl[0][brow * BSTRIDE + bcol],
                                &Blg[(size_t)(k0 + brow) * N + bn + bcol], 16);
        __pipeline_commit();
    }

    for (int ks = 0; ks < nk; ks++) {
        __pipeline_wait_prior(0);
        __syncthreads();

        if (ks + 1 < nk) {
            const int k0 = (ks + 1) << 4;
            const int st = (ks + 1) & 1;
            __pipeline_memcpy_async(&sAh[st][arow * ASTRIDE + acol],
                                    &Ahg[(size_t)(bm + arow) * K + k0 + acol], 16);
            __pipeline_memcpy_async(&sAl[st][arow * ASTRIDE + acol],
                                    &Alg[(size_t)(bm + arow) * K + k0 + acol], 16);
            __pipeline_memcpy_async(&sBh[st][brow * BSTRIDE + bcol],
                                    &Bhg[(size_t)(k0 + brow) * N + bn + bcol], 16);
            __pipeline_memcpy_async(&sBl[st][brow * BSTRIDE + bcol],
                                    &Blg[(size_t)(k0 + brow) * N + bn + bcol], 16);
            __pipeline_commit();
        }

        const int cur = ks & 1;
        wmma::fragment<wmma::matrix_a, 16, 16, 16, __nv_bfloat16, wmma::row_major> fa_h[2];
        wmma::fragment<wmma::matrix_a, 16, 16, 16, __nv_bfloat16, wmma::row_major> fa_l[2];
        wmma::fragment<wmma::matrix_b, 16, 16, 16, __nv_bfloat16, wmma::row_major> fb_h[4];
        wmma::fragment<wmma::matrix_b, 16, 16, 16, __nv_bfloat16, wmma::row_major> fb_l[4];
#pragma unroll
        for (int mt = 0; mt < 2; mt++) {
            const __nv_bfloat16* pa = &sAh[cur][(wm * 32 + mt * 16) * ASTRIDE];
            wmma::load_matrix_sync(fa_h[mt], pa, ASTRIDE);
            const __nv_bfloat16* pl = &sAl[cur][(wm * 32 + mt * 16) * ASTRIDE];
            wmma::load_matrix_sync(fa_l[mt], pl, ASTRIDE);
        }
#pragma unroll
        for (int nt = 0; nt < 4; nt++) {
            const __nv_bfloat16* pb = &sBh[cur][wn * 64 + nt * 16];
            wmma::load_matrix_sync(fb_h[nt], pb, BSTRIDE);
            const __nv_bfloat16* pl = &sBl[cur][wn * 64 + nt * 16];
            wmma::load_matrix_sync(fb_l[nt], pl, BSTRIDE);
        }
#pragma unroll
        for (int mt = 0; mt < 2; mt++) {
#pragma unroll
            for (int nt = 0; nt < 4; nt++) {
                wmma::mma_sync(acc[mt][nt], fa_h[mt], fb_h[nt], acc[mt][nt]);
                wmma::mma_sync(acc[mt][nt], fa_h[mt], fb_l[nt], acc[mt][nt]);
                wmma::mma_sync(acc[mt][nt], fa_l[mt], fb_h[nt], acc[mt][nt]);
            }
        }
    }

#pragma unroll
    for (int mt = 0; mt < 2; mt++) {
        int row0 = bm + wm * 32 + mt * 16;
#pragma unroll
        for (int nt = 0; nt < 4; nt++) {
            int col0 = bn + wn * 64 + nt * 16;
            float* dst = &Cm[(size_t)row0 * N + col0];
            wmma::store_matrix_sync(dst, acc[mt][nt], N, wmma::mem_row_major);
        }
    }
}

// ---------------------------------------------------------------------------
// RoPE in place on q and k slices of g_qkv.
// ---------------------------------------------------------------------------
__global__ __launch_bounds__(256)
void rope_kernel(float* __restrict__ qkv)
{
    int idx = blockIdx.x * blockDim.x + threadIdx.x;
    int d2 = idx & 31;
    int h  = (idx >> 5) & (NH - 1);
    int t  = (idx >> 9) & (TT - 1);
    int b  = idx >> 20;
    if (b >= BB) return;

    float invf = 1.0f / powf(10000.0f, (float)d2 / 32.0f);
    float ang  = (float)t * invf;
    float c = (float)cos((double)ang);
    float s = (float)sin((double)ang);

    size_t base = (size_t)(b * TT + t) * C3 + h * HD;
#pragma unroll
    for (int part = 0; part < 2; part++) {
        float* p = qkv + base + part * CC;
        float a0 = p[d2];
        float a1 = p[d2 + 32];
        p[d2]      = a0 * c - a1 * s;
        p[d2 + 32] = a1 * c + a0 * s;
    }
}

// ---------------------------------------------------------------------------
// Windowed causal attention with sinks. Conflict-free smem layout.
// ---------------------------------------------------------------------------
#define CHUNK 32
#define QKV_STRIDE 68
#define PS_STRIDE 36

__global__ __launch_bounds__(256)
void attn_kernel(const float* __restrict__ qkv, float* __restrict__ att)
{
    __shared__ float Qs[64 * QKV_STRIDE];
    __shared__ float Ks[CHUNK * QKV_STRIDE];
    __shared__ float Vs[CHUNK * QKV_STRIDE];
    __shared__ float Ps[64 * PS_STRIDE];

    const int tid = threadIdx.x;
    const int bid = blockIdx.x;
    const int qb = bid & 31;
    const int h  = (bid >> 5) & (NH - 1);
    const int b  = bid >> 9;
    const int q0 = qb * 64;
    const int sq = tid >> 2;
    const int kt = tid & 3;
    const float scale = 0.125f;

#pragma unroll
    for (int i = 0; i < 4; i++) {
        int f = tid + i * 256;
        int r = f >> 4;
        int c4 = (f & 15) << 2;
        const float* src = &qkv[(size_t)(b * TT + q0 + r) * C3 + h * HD + c4];
        float4 v = *reinterpret_cast<const float4*>(src);
        v.x *= scale;
        v.y *= scale;
        v.z *= scale;
        v.w *= scale;
        *reinterpret_cast<float4*>(&Qs[r * QKV_STRIDE + c4]) = v;
    }

    float m = -1e30f;
    float l = 0.f;
    float o[16];
#pragma unroll
    for (int i = 0; i < 16; i++) o[i] = 0.f;

    const int cstart = (q0 - WINDOW > 0) ? (q0 - WINDOW) : 0;
    const int do_sink = (cstart > 0) ? 1 : 0;
    const int nwin = (q0 + 64 - cstart) / CHUNK;
    const int nch = nwin + do_sink;

    for (int phase = 0; phase < nch; phase++) {
        const int c = (do_sink && phase == 0) ? 0 : cstart + (phase - do_sink) * CHUNK;

        __syncthreads();
#pragma unroll
        for (int i = 0; i < 2; i++) {
            int f = tid + i * 256;
            int r = f >> 4;
            int c4 = (f & 15) << 2;
            size_t rowbase = (size_t)(b * TT + c + r) * C3 + h * HD + c4;
            const float* srck = &qkv[rowbase + CC];
            *reinterpret_cast<float4*>(&Ks[r * QKV_STRIDE + c4]) =
                *reinterpret_cast<const float4*>(srck);
            const float* srcv = &qkv[rowbase + 2 * CC];
            *reinterpret_cast<float4*>(&Vs[r * QKV_STRIDE + c4]) =
                *reinterpret_cast<const float4*>(srcv);
        }
        __syncthreads();

        float s[8];
#pragma unroll
        for (int i = 0; i < 8; i++) s[i] = 0.f;
#pragma unroll
        for (int d4 = 0; d4 < 16; d4++) {
            float4 qv = *reinterpret_cast<const float4*>(&Qs[sq * QKV_STRIDE + d4 * 4]);
#pragma unroll
            for (int kki = 0; kki < 8; kki++) {
                const float* kp = &Ks[(kt + kki * 4) * QKV_STRIDE + d4 * 4];
                float4 kv = *reinterpret_cast<const float4*>(kp);
                s[kki] += qv.x * kv.x + qv.y * kv.y + qv.z * kv.z + qv.w * kv.w;
            }
        }
        const int q = q0 + sq;
        float mc = -1e30f;
#pragma unroll
        for (int kki = 0; kki < 8; kki++) {
            int j = c + kt + kki * 4;
            bool allowed = (j <= q) && (((q - j) < WINDOW) || (j < SINK));
            if (!allowed) s[kki] = -1e30f;
            mc = fmaxf(mc, s[kki]);
        }
        mc = fmaxf(mc, __shfl_xor_sync(0xffffffffu, mc, 1));
        mc = fmaxf(mc, __shfl_xor_sync(0xffffffffu, mc, 2));
        float mn = fmaxf(m, mc);
        float alpha = expf(m - mn);

        float lc = 0.f;
#pragma unroll
        for (int kki = 0; kki < 8; kki++) {
            float p = expf(s[kki] - mn);
            lc += p;
            Ps[sq * PS_STRIDE + kt + kki * 4] = p;
        }
        lc += __shfl_xor_sync(0xffffffffu, lc, 1);
        lc += __shfl_xor_sync(0xffffffffu, lc, 2);
        l = l * alpha + lc;
        m = mn;

        __syncthreads();

#pragma unroll
        for (int i = 0; i < 16; i++) o[i] *= alpha;
        for (int j = 0; j < CHUNK; j++) {
            float p = Ps[sq * PS_STRIDE + j];
#pragma unroll
            for (int i4 = 0; i4 < 4; i4++) {
                const float* vp = &Vs[j * QKV_STRIDE + kt * 4 + i4 * 16];
                float4 v = *reinterpret_cast<const float4*>(vp);
                o[i4 * 4 + 0] += p * v.x;
                o[i4 * 4 + 1] += p * v.y;
                o[i4 * 4 + 2] += p * v.z;
                o[i4 * 4 + 3] += p * v.w;
            }
        }
    }

    float inv = 1.0f / l;
    size_t obase = (size_t)(b * TT + q0 + sq) * CC + h * HD + kt * 4;
#pragma unroll
    for (int i4 = 0; i4 < 4; i4++) {
        float4 v = make_float4(o[i4 * 4] * inv, o[i4 * 4 + 1] * inv,
                               o[i4 * 4 + 2] * inv, o[i4 * 4 + 3] * inv);
        *reinterpret_cast<float4*>(&att[obase + i4 * 16]) = v;
    }
}

// ---------------------------------------------------------------------------
extern "C" void kernel_launch(void* const* d_in, const int* in_sizes, int n_in,
                              void* d_out, int out_size)
{
    const float* x = nullptr;
    const float* w_attn = nullptr;
    const float* w_proj = nullptr;
    for (int i = 0; i < n_in; i++) {
        if (in_sizes[i] == BB * TT * CC)      x      = (const float*)d_in[i];
        else if (in_sizes[i] == CC * C3)      w_attn = (const float*)d_in[i];
        else if (in_sizes[i] == CC * CC)      w_proj = (const float*)d_in[i];
    }
    if (!x || !w_attn || !w_proj) {
        x      = (const float*)d_in[0];
        w_attn = (const float*)d_in[1];
        w_proj = (const float*)d_in[2];
    }
    float* out = (float*)d_out;

    void* p;
    cudaGetSymbolAddress(&p, g_qkv);
    float* qkv = (float*)p;
    cudaGetSymbolAddress(&p, g_att);
    float* att = (float*)p;
    cudaGetSymbolAddress(&p, g_xh);
    __nv_bfloat16* xh = (__nv_bfloat16*)p;
    cudaGetSymbolAddress(&p, g_xl);
    __nv_bfloat16* xl = (__nv_bfloat16*)p;
    cudaGetSymbolAddress(&p, g_wah);
    __nv_bfloat16* wah = (__nv_bfloat16*)p;
    cudaGetSymbolAddress(&p, g_wal);
    __nv_bfloat16* wal = (__nv_bfloat16*)p;
    cudaGetSymbolAddress(&p, g_wph);
    __nv_bfloat16* wph = (__nv_bfloat16*)p;
    cudaGetSymbolAddress(&p, g_wpl);
    __nv_bfloat16* wpl = (__nv_bfloat16*)p;
    cudaGetSymbolAddress(&p, g_ath);
    __nv_bfloat16* ath = (__nv_bfloat16*)p;
    cudaGetSymbolAddress(&p, g_atl);
    __nv_bfloat16* atl = (__nv_bfloat16*)p;

    // splits
    {
        int n4 = (MROWS * CC) / 4;
        split_kernel<<<(n4 + 255) / 256, 256>>>(x, xh, xl, n4);
    }
    {
        int n4 = (CC * C3) / 4;
        split_kernel<<<(n4 + 255) / 256, 256>>>(w_attn, wah, wal, n4);
    }
    {
        int n4 = (CC * CC) / 4;
        split_kernel<<<(n4 + 255) / 256, 256>>>(w_proj, wph, wpl, n4);
    }
    // qkv = x @ w_attn
    {
        dim3 grid(C3 / 128, MROWS / 128);
        gemm_tc_kernel<<<grid, 256>>>(xh, xl, wah, wal, qkv, MROWS, C3, CC);
    }
    // RoPE
    {
        int total = BB * TT * NH * 32;
        rope_kernel<<<total / 256, 256>>>(qkv);
    }
    // attention
    {
        int grid = BB * NH * (TT / 64);
        attn_kernel<<<grid, 256>>>(qkv, att);
    }
    // split attention output
    {
        int n4 = (MROWS * CC) / 4;
        split_kernel<<<(n4 + 255) / 256, 256>>>(att, ath, atl, n4);
    }
    // out = att @ w_proj
    {
        dim3 grid(CC / 128, MROWS / 128);
        gemm_tc_kernel<<<grid, 256>>>(ath, atl, wph, wpl, out, MROWS, CC, CC);
    }
}

// round 11
// speedup vs baseline: 2.7376x; 1.1809x over previous
#include <cuda_runtime.h>
#include <cuda_bf16.h>
#include <cuda_pipeline.h>
#include <mma.h>
#include <math.h>

using namespace nvcuda;

// Problem constants
#define BB 2
#define TT 2048
#define CC 1024
#define NH 16
#define HD 64
#define WINDOW 256
#define SINK 4
#define MROWS (BB*TT)
#define C3 (3*CC)

// Scratch (device globals: no allocation allowed)
__device__ float g_qkv[MROWS * C3];
__device__ __nv_bfloat16 g_xh[MROWS * CC];
__device__ __nv_bfloat16 g_xl[MROWS * CC];
__device__ __nv_bfloat16 g_wah[CC * C3];
__device__ __nv_bfloat16 g_wal[CC * C3];
__device__ __nv_bfloat16 g_wph[CC * CC];
__device__ __nv_bfloat16 g_wpl[CC * CC];
__device__ __nv_bfloat16 g_ath[MROWS * CC];
__device__ __nv_bfloat16 g_atl[MROWS * CC];

// ---------------------------------------------------------------------------
// Split fp32 -> bf16 hi + bf16 lo (residual). Vectorized float4 per thread.
// ---------------------------------------------------------------------------
__global__ __launch_bounds__(256)
void split_kernel(const float* __restrict__ src,
                  __nv_bfloat16* __restrict__ dh,
                  __nv_bfloat16* __restrict__ dl, int n4)
{
    int idx = blockIdx.x * blockDim.x + threadIdx.x;
    if (idx >= n4) return;
    float4 v = reinterpret_cast<const float4*>(src)[idx];
    float vals[4];
    vals[0] = v.x;
    vals[1] = v.y;
    vals[2] = v.z;
    vals[3] = v.w;
    unsigned short hs[4];
    unsigned short ls[4];
#pragma unroll
    for (int i = 0; i < 4; i++) {
        __nv_bfloat16 hb = __float2bfloat16(vals[i]);
        float r = vals[i] - __bfloat162float(hb);
        __nv_bfloat16 lb = __float2bfloat16(r);
        hs[i] = __bfloat16_as_ushort(hb);
        ls[i] = __bfloat16_as_ushort(lb);
    }
    uint2 hp;
    hp.x = (uint32_t)hs[0] | ((uint32_t)hs[1] << 16);
    hp.y = (uint32_t)hs[2] | ((uint32_t)hs[3] << 16);
    uint2 lp;
    lp.x = (uint32_t)ls[0] | ((uint32_t)ls[1] << 16);
    lp.y = (uint32_t)ls[2] | ((uint32_t)ls[3] << 16);
    reinterpret_cast<uint2*>(dh)[idx] = hp;
    reinterpret_cast<uint2*>(dl)[idx] = lp;
}

// ===========================================================================
// Double-buffered split-bf16 GEMM: C = (Ah+Al) @ (Bh+Bl) (3-pass), fp32 acc.
// Block 128x128, BK=16, 8 warps (warp tile 32x64), cp.async 2-stage pipeline.
// ===========================================================================
#define ASTRIDE 24
#define BSTRIDE 136

__global__ __launch_bounds__(256)
void gemm_tc_kernel(const __nv_bfloat16* __restrict__ Ahg,
                    const __nv_bfloat16* __restrict__ Alg,
                    const __nv_bfloat16* __restrict__ Bhg,
                    const __nv_bfloat16* __restrict__ Blg,
                    float* __restrict__ Cm, int M, int N, int K)
{
    __shared__ __nv_bfloat16 sAh[2][128 * ASTRIDE];
    __shared__ __nv_bfloat16 sAl[2][128 * ASTRIDE];
    __shared__ __nv_bfloat16 sBh[2][16 * BSTRIDE];
    __shared__ __nv_bfloat16 sBl[2][16 * BSTRIDE];

    const int tid  = threadIdx.x;
    const int warp = tid >> 5;
    const int wm = warp & 3;
    const int wn = warp >> 2;
    const int bm = blockIdx.y * 128;
    const int bn = blockIdx.x * 128;

    const int arow = tid >> 1;
    const int acol = (tid & 1) << 3;
    const int brow = tid >> 4;
    const int bcol = (tid & 15) << 3;

    wmma::fragment<wmma::accumulator, 16, 16, 16, float> acc[2][4];
#pragma unroll
    for (int mt = 0; mt < 2; mt++) {
#pragma unroll
        for (int nt = 0; nt < 4; nt++) {
            wmma::fill_fragment(acc[mt][nt], 0.0f);
        }
    }

    const int nk = K >> 4;

    {
        const int k0 = 0;
        __pipeline_memcpy_async(&sAh[0][arow * ASTRIDE + acol],
                                &Ahg[(size_t)(bm + arow) * K + k0 + acol], 16);
        __pipeline_memcpy_async(&sAl[0][arow * ASTRIDE + acol],
                                &Alg[(size_t)(bm + arow) * K + k0 + acol], 16);
        __pipeline_memcpy_async(&sBh[0][brow * BSTRIDE + bcol],
                                &Bhg[(size_t)(k0 + brow) * N + bn + bcol], 16);
        __pipeline_memcpy_async(&sBl[0][brow * BSTRIDE + bcol],
                                &Blg[(size_t)(k0 + brow) * N + bn + bcol], 16);
        __pipeline_commit();
    }

    for (int ks = 0; ks < nk; ks++) {
        __pipeline_wait_prior(0);
        __syncthreads();

        if (ks + 1 < nk) {
            const int k0 = (ks + 1) << 4;
            const int st = (ks + 1) & 1;
            __pipeline_memcpy_async(&sAh[st][arow * ASTRIDE + acol],
                                    &Ahg[(size_t)(bm + arow) * K + k0 + acol], 16);
            __pipeline_memcpy_async(&sAl[st][arow * ASTRIDE + acol],
                                    &Alg[(size_t)(bm + arow) * K + k0 + acol], 16);
            __pipeline_memcpy_async(&sBh[st][brow * BSTRIDE + bcol],
                                    &Bhg[(size_t)(k0 + brow) * N + bn + bcol], 16);
            __pipeline_memcpy_async(&sBl[st][brow * BSTRIDE + bcol],
                                    &Blg[(size_t)(k0 + brow) * N + bn + bcol], 16);
            __pipeline_commit();
        }

        const int cur = ks & 1;
        wmma::fragment<wmma::matrix_a, 16, 16, 16, __nv_bfloat16, wmma::row_major> fa_h[2];
        wmma::fragment<wmma::matrix_a, 16, 16, 16, __nv_bfloat16, wmma::row_major> fa_l[2];
        wmma::fragment<wmma::matrix_b, 16, 16, 16, __nv_bfloat16, wmma::row_major> fb_h[4];
        wmma::fragment<wmma::matrix_b, 16, 16, 16, __nv_bfloat16, wmma::row_major> fb_l[4];
#pragma unroll
        for (int mt = 0; mt < 2; mt++) {
            const __nv_bfloat16* pa = &sAh[cur][(wm * 32 + mt * 16) * ASTRIDE];
            wmma::load_matrix_sync(fa_h[mt], pa, ASTRIDE);
            const __nv_bfloat16* pl = &sAl[cur][(wm * 32 + mt * 16) * ASTRIDE];
            wmma::load_matrix_sync(fa_l[mt], pl, ASTRIDE);
        }
#pragma unroll
        for (int nt = 0; nt < 4; nt++) {
            const __nv_bfloat16* pb = &sBh[cur][wn * 64 + nt * 16];
            wmma::load_matrix_sync(fb_h[nt], pb, BSTRIDE);
            const __nv_bfloat16* pl = &sBl[cur][wn * 64 + nt * 16];
            wmma::load_matrix_sync(fb_l[nt], pl, BSTRIDE);
        }
#pragma unroll
        for (int mt = 0; mt < 2; mt++) {
#pragma unroll
            for (int nt = 0; nt < 4; nt++) {
                wmma::mma_sync(acc[mt][nt], fa_h[mt], fb_h[nt], acc[mt][nt]);
                wmma::mma_sync(acc[mt][nt], fa_h[mt], fb_l[nt], acc[mt][nt]);
                wmma::mma_sync(acc[mt][nt], fa_l[mt], fb_h[nt], acc[mt][nt]);
            }
        }
    }

#pragma unroll
    for (int mt = 0; mt < 2; mt++) {
        int row0 = bm + wm * 32 + mt * 16;
#pragma unroll
        for (int nt = 0; nt < 4; nt++) {
            int col0 = bn + wn * 64 + nt * 16;
            float* dst = &Cm[(size_t)row0 * N + col0];
            wmma::store_matrix_sync(dst, acc[mt][nt], N, wmma::mem_row_major);
        }
    }
}

// ---------------------------------------------------------------------------
// RoPE in place on q and k slices of g_qkv.
// ---------------------------------------------------------------------------
__global__ __launch_bounds__(256)
void rope_kernel(float* __restrict__ qkv)
{
    int idx = blockIdx.x * blockDim.x + threadIdx.x;
    int d2 = idx & 31;
    int h  = (idx >> 5) & (NH - 1);
    int t  = (idx >> 9) & (TT - 1);
    int b  = idx >> 20;
    if (b >= BB) return;

    float invf = 1.0f / powf(10000.0f, (float)d2 / 32.0f);
    float ang  = (float)t * invf;
    float c = (float)cos((double)ang);
    float s = (float)sin((double)ang);

    size_t base = (size_t)(b * TT + t) * C3 + h * HD;
#pragma unroll
    for (int part = 0; part < 2; part++) {
        float* p = qkv + base + part * CC;
        float a0 = p[d2];
        float a1 = p[d2 + 32];
        p[d2]      = a0 * c - a1 * s;
        p[d2 + 32] = a1 * c + a0 * s;
    }
}

// ---------------------------------------------------------------------------
// Windowed causal attention, 2 queries/thread, conflict-free smem.
// Thread (sq = tid>>3 in [0,32), kt = tid&7): queries sq and sq+32;
// scoring 4 keys (j = kt + kki*8); PV dims kt*4..+3 and kt*4+32..+35.
// Epilogue writes bf16 hi/lo directly (fused split for proj GEMM).
// ---------------------------------------------------------------------------
#define CHUNK 32
#define QKV_STRIDE 68
#define PS_STRIDE 36

__global__ __launch_bounds__(256)
void attn_kernel(const float* __restrict__ qkv,
                 __nv_bfloat16* __restrict__ ath,
                 __nv_bfloat16* __restrict__ atl)
{
    __shared__ float Qs[64 * QKV_STRIDE];
    __shared__ float Ks[CHUNK * QKV_STRIDE];
    __shared__ float Vs[CHUNK * QKV_STRIDE];
    __shared__ float Ps[64 * PS_STRIDE];

    const int tid = threadIdx.x;
    const int bid = blockIdx.x;
    const int qb = bid & 31;
    const int h  = (bid >> 5) & (NH - 1);
    const int b  = bid >> 9;
    const int q0 = qb * 64;
    const int sq = tid >> 3;          // 0..31
    const int kt = tid & 7;           // 0..7
    const float scale = 0.125f;

#pragma unroll
    for (int i = 0; i < 4; i++) {
        int f = tid + i * 256;
        int r = f >> 4;
        int c4 = (f & 15) << 2;
        const float* src = &qkv[(size_t)(b * TT + q0 + r) * C3 + h * HD + c4];
        float4 v = *reinterpret_cast<const float4*>(src);
        v.x *= scale;
        v.y *= scale;
        v.z *= scale;
        v.w *= scale;
        *reinterpret_cast<float4*>(&Qs[r * QKV_STRIDE + c4]) = v;
    }

    float m1 = -1e30f;
    float l1 = 0.f;
    float m2 = -1e30f;
    float l2 = 0.f;
    float o1[8];
    float o2[8];
#pragma unroll
    for (int i = 0; i < 8; i++) {
        o1[i] = 0.f;
        o2[i] = 0.f;
    }

    const int cstart = (q0 - WINDOW > 0) ? (q0 - WINDOW) : 0;
    const int do_sink = (cstart > 0) ? 1 : 0;
    const int nwin = (q0 + 64 - cstart) / CHUNK;
    const int nch = nwin + do_sink;

    for (int phase = 0; phase < nch; phase++) {
        const int c = (do_sink && phase == 0) ? 0 : cstart + (phase - do_sink) * CHUNK;

        __syncthreads();
#pragma unroll
        for (int i = 0; i < 2; i++) {
            int f = tid + i * 256;
            int r = f >> 4;
            int c4 = (f & 15) << 2;
            size_t rowbase = (size_t)(b * TT + c + r) * C3 + h * HD + c4;
            const float* srck = &qkv[rowbase + CC];
            *reinterpret_cast<float4*>(&Ks[r * QKV_STRIDE + c4]) =
                *reinterpret_cast<const float4*>(srck);
            const float* srcv = &qkv[rowbase + 2 * CC];
            *reinterpret_cast<float4*>(&Vs[r * QKV_STRIDE + c4]) =
                *reinterpret_cast<const float4*>(srcv);
        }
        __syncthreads();

        float s1[4];
        float s2[4];
#pragma unroll
        for (int i = 0; i < 4; i++) {
            s1[i] = 0.f;
            s2[i] = 0.f;
        }
#pragma unroll
        for (int d4 = 0; d4 < 16; d4++) {
            float4 q1 = *reinterpret_cast<const float4*>(&Qs[sq * QKV_STRIDE + d4 * 4]);
            float4 q2 = *reinterpret_cast<const float4*>(&Qs[(sq + 32) * QKV_STRIDE + d4 * 4]);
#pragma unroll
            for (int kki = 0; kki < 4; kki++) {
                const float* kp = &Ks[(kt + kki * 8) * QKV_STRIDE + d4 * 4];
                float4 kv = *reinterpret_cast<const float4*>(kp);
                s1[kki] += q1.x * kv.x + q1.y * kv.y + q1.z * kv.z + q1.w * kv.w;
                s2[kki] += q2.x * kv.x + q2.y * kv.y + q2.z * kv.z + q2.w * kv.w;
            }
        }
        const int qq1 = q0 + sq;
        const int qq2 = q0 + sq + 32;
        float mc1 = -1e30f;
        float mc2 = -1e30f;
#pragma unroll
        for (int kki = 0; kki < 4; kki++) {
            int j = c + kt + kki * 8;
            bool a1 = (j <= qq1) && (((qq1 - j) < WINDOW) || (j < SINK));
            if (!a1) s1[kki] = -1e30f;
            mc1 = fmaxf(mc1, s1[kki]);
            bool a2 = (j <= qq2) && (((qq2 - j) < WINDOW) || (j < SINK));
            if (!a2) s2[kki] = -1e30f;
            mc2 = fmaxf(mc2, s2[kki]);
        }
        mc1 = fmaxf(mc1, __shfl_xor_sync(0xffffffffu, mc1, 1));
        mc1 = fmaxf(mc1, __shfl_xor_sync(0xffffffffu, mc1, 2));
        mc1 = fmaxf(mc1, __shfl_xor_sync(0xffffffffu, mc1, 4));
        mc2 = fmaxf(mc2, __shfl_xor_sync(0xffffffffu, mc2, 1));
        mc2 = fmaxf(mc2, __shfl_xor_sync(0xffffffffu, mc2, 2));
        mc2 = fmaxf(mc2, __shfl_xor_sync(0xffffffffu, mc2, 4));
        float mn1 = fmaxf(m1, mc1);
        float mn2 = fmaxf(m2, mc2);
        float alpha1 = expf(m1 - mn1);
        float alpha2 = expf(m2 - mn2);

        float lc1 = 0.f;
        float lc2 = 0.f;
#pragma unroll
        for (int kki = 0; kki < 4; kki++) {
            float p1 = expf(s1[kki] - mn1);
            lc1 += p1;
            Ps[sq * PS_STRIDE + kt + kki * 8] = p1;
            float p2 = expf(s2[kki] - mn2);
            lc2 += p2;
            Ps[(sq + 32) * PS_STRIDE + kt + kki * 8] = p2;
        }
        lc1 += __shfl_xor_sync(0xffffffffu, lc1, 1);
        lc1 += __shfl_xor_sync(0xffffffffu, lc1, 2);
        lc1 += __shfl_xor_sync(0xffffffffu, lc1, 4);
        lc2 += __shfl_xor_sync(0xffffffffu, lc2, 1);
        lc2 += __shfl_xor_sync(0xffffffffu, lc2, 2);
        lc2 += __shfl_xor_sync(0xffffffffu, lc2, 4);
        l1 = l1 * alpha1 + lc1;
        l2 = l2 * alpha2 + lc2;
        m1 = mn1;
        m2 = mn2;

        __syncthreads();

#pragma unroll
        for (int i = 0; i < 8; i++) {
            o1[i] *= alpha1;
            o2[i] *= alpha2;
        }
        for (int j = 0; j < CHUNK; j++) {
            float p1 = Ps[sq * PS_STRIDE + j];
            float p2 = Ps[(sq + 32) * PS_STRIDE + j];
            const float* vpa = &Vs[j * QKV_STRIDE + kt * 4];
            float4 va = *reinterpret_cast<const float4*>(vpa);
            const float* vpb = &Vs[j * QKV_STRIDE + kt * 4 + 32];
            float4 vb = *reinterpret_cast<const float4*>(vpb);
            o1[0] += p1 * va.x;
            o1[1] += p1 * va.y;
            o1[2] += p1 * va.z;
            o1[3] += p1 * va.w;
            o1[4] += p1 * vb.x;
            o1[5] += p1 * vb.y;
            o1[6] += p1 * vb.z;
            o1[7] += p1 * vb.w;
            o2[0] += p2 * va.x;
            o2[1] += p2 * va.y;
            o2[2] += p2 * va.z;
            o2[3] += p2 * va.w;
            o2[4] += p2 * vb.x;
            o2[5] += p2 * vb.y;
            o2[6] += p2 * vb.z;
            o2[7] += p2 * vb.w;
        }
    }

    // epilogue: normalize and write bf16 hi/lo directly
    float inv1 = 1.0f / l1;
    float inv2 = 1.0f / l2;
#pragma unroll
    for (int qi = 0; qi < 2; qi++) {
        float inv = (qi == 0) ? inv1 : inv2;
        const float* oo = (qi == 0) ? o1 : o2;
        size_t rowbase = (size_t)(b * TT + q0 + sq + qi * 32) * CC + h * HD;
#pragma unroll
        for (int half = 0; half < 2; half++) {
            unsigned short hs[4];
            unsigned short ls[4];
#pragma unroll
            for (int e = 0; e < 4; e++) {
                float val = oo[half * 4 + e] * inv;
                __nv_bfloat16 hb = __float2bfloat16(val);
                float r = val - __bfloat162float(hb);
                __nv_bfloat16 lb = __float2bfloat16(r);
                hs[e] = __bfloat16_as_ushort(hb);
                ls[e] = __bfloat16_as_ushort(lb);
            }
            uint2 hp;
            hp.x = (uint32_t)hs[0] | ((uint32_t)hs[1] << 16);
            hp.y = (uint32_t)hs[2] | ((uint32_t)hs[3] << 16);
            uint2 lp;
            lp.x = (uint32_t)ls[0] | ((uint32_t)ls[1] << 16);
            lp.y = (uint32_t)ls[2] | ((uint32_t)ls[3] << 16);
            size_t off = rowbase + kt * 4 + half * 32;
            *reinterpret_cast<uint2*>(&ath[off]) = hp;
            *reinterpret_cast<uint2*>(&atl[off]) = lp;
        }
    }
}

// ---------------------------------------------------------------------------
extern "C" void kernel_launch(void* const* d_in, const int* in_sizes, int n_in,
                              void* d_out, int out_size)
{
    const float* x = nullptr;
    const float* w_attn = nullptr;
    const float* w_proj = nullptr;
    for (int i = 0; i < n_in; i++) {
        if (in_sizes[i] == BB * TT * CC)      x      = (const float*)d_in[i];
        else if (in_sizes[i] == CC * C3)      w_attn = (const float*)d_in[i];
        else if (in_sizes[i] == CC * CC)      w_proj = (const float*)d_in[i];
    }
    if (!x || !w_attn || !w_proj) {
        x      = (const float*)d_in[0];
        w_attn = (const float*)d_in[1];
        w_proj = (const float*)d_in[2];
    }
    float* out = (float*)d_out;

    void* p;
    cudaGetSymbolAddress(&p, g_qkv);
    float* qkv = (float*)p;
    cudaGetSymbolAddress(&p, g_xh);
    __nv_bfloat16* xh = (__nv_bfloat16*)p;
    cudaGetSymbolAddress(&p, g_xl);
    __nv_bfloat16* xl = (__nv_bfloat16*)p;
    cudaGetSymbolAddress(&p, g_wah);
    __nv_bfloat16* wah = (__nv_bfloat16*)p;
    cudaGetSymbolAddress(&p, g_wal);
    __nv_bfloat16* wal = (__nv_bfloat16*)p;
    cudaGetSymbolAddress(&p, g_wph);
    __nv_bfloat16* wph = (__nv_bfloat16*)p;
    cudaGetSymbolAddress(&p, g_wpl);
    __nv_bfloat16* wpl = (__nv_bfloat16*)p;
    cudaGetSymbolAddress(&p, g_ath);
    __nv_bfloat16* ath = (__nv_bfloat16*)p;
    cudaGetSymbolAddress(&p, g_atl);
    __nv_bfloat16* atl = (__nv_bfloat16*)p;

    // splits of inputs
    {
        int n4 = (MROWS * CC) / 4;
        split_kernel<<<(n4 + 255) / 256, 256>>>(x, xh, xl, n4);
    }
    {
        int n4 = (CC * C3) / 4;
        split_kernel<<<(n4 + 255) / 256, 256>>>(w_attn, wah, wal, n4);
    }
    {
        int n4 = (CC * CC) / 4;
        split_kernel<<<(n4 + 255) / 256, 256>>>(w_proj, wph, wpl, n4);
    }
    // qkv = x @ w_attn
    {
        dim3 grid(C3 / 128, MROWS / 128);
        gemm_tc_kernel<<<grid, 256>>>(xh, xl, wah, wal, qkv, MROWS, C3, CC);
    }
    // RoPE
    {
        int total = BB * TT * NH * 32;
        rope_kernel<<<total / 256, 256>>>(qkv);
    }
    // attention (writes bf16 hi/lo directly)
    {
        int grid = BB * NH * (TT / 64);
        attn_kernel<<<grid, 256>>>(qkv, ath, atl);
    }
    // out = att @ w_proj
    {
        dim3 grid(CC / 128, MROWS / 128);
        gemm_tc_kernel<<<grid, 256>>>(ath, atl, wph, wpl, out, MROWS, CC, CC);
    }
}

// round 12
// speedup vs baseline: 2.9091x; 1.0626x over previous
#include <cuda_runtime.h>
#include <cuda_bf16.h>
#include <cuda_pipeline.h>
#include <mma.h>
#include <math.h>

using namespace nvcuda;

// Problem constants
#define BB 2
#define TT 2048
#define CC 1024
#define NH 16
#define HD 64
#define WINDOW 256
#define SINK 4
#define MROWS (BB*TT)
#define C3 (3*CC)

// Scratch (device globals: no allocation allowed)
__device__ float g_qkv[MROWS * C3];
__device__ __nv_bfloat16 g_xh[MROWS * CC];
__device__ __nv_bfloat16 g_xl[MROWS * CC];
__device__ __nv_bfloat16 g_wah[CC * C3];
__device__ __nv_bfloat16 g_wal[CC * C3];
__device__ __nv_bfloat16 g_wph[CC * CC];
__device__ __nv_bfloat16 g_wpl[CC * CC];
__device__ __nv_bfloat16 g_ath[MROWS * CC];
__device__ __nv_bfloat16 g_atl[MROWS * CC];

// ---------------------------------------------------------------------------
// Split fp32 -> bf16 hi + bf16 lo (residual). Vectorized float4 per thread.
// ---------------------------------------------------------------------------
__global__ __launch_bounds__(256)
void split_kernel(const float* __restrict__ src,
                  __nv_bfloat16* __restrict__ dh,
                  __nv_bfloat16* __restrict__ dl, int n4)
{
    int idx = blockIdx.x * blockDim.x + threadIdx.x;
    if (idx >= n4) return;
    float4 v = reinterpret_cast<const float4*>(src)[idx];
    float vals[4];
    vals[0] = v.x;
    vals[1] = v.y;
    vals[2] = v.z;
    vals[3] = v.w;
    unsigned short hs[4];
    unsigned short ls[4];
#pragma unroll
    for (int i = 0; i < 4; i++) {
        __nv_bfloat16 hb = __float2bfloat16(vals[i]);
        float r = vals[i] - __bfloat162float(hb);
        __nv_bfloat16 lb = __float2bfloat16(r);
        hs[i] = __bfloat16_as_ushort(hb);
        ls[i] = __bfloat16_as_ushort(lb);
    }
    uint2 hp;
    hp.x = (uint32_t)hs[0] | ((uint32_t)hs[1] << 16);
    hp.y = (uint32_t)hs[2] | ((uint32_t)hs[3] << 16);
    uint2 lp;
    lp.x = (uint32_t)ls[0] | ((uint32_t)ls[1] << 16);
    lp.y = (uint32_t)ls[2] | ((uint32_t)ls[3] << 16);
    reinterpret_cast<uint2*>(dh)[idx] = hp;
    reinterpret_cast<uint2*>(dl)[idx] = lp;
}

// ===========================================================================
// Double-buffered split-bf16 GEMM: C = (Ah+Al) @ (Bh+Bl) (3-pass), fp32 acc.
// Block 128x128, BK=32, 8 warps (warp tile 32x64), cp.async 2-stage pipeline.
// Dynamic smem (74KB): halves iteration/sync count vs BK=16.
// ===========================================================================
#define GASTRIDE 40     // bf16 elems per A smem row (32 + 8 pad)
#define GBSTRIDE 136    // bf16 elems per B smem row (128 + 8 pad)
#define SA_STAGE (128 * GASTRIDE)   // 5120
#define SB_STAGE (32 * GBSTRIDE)    // 4352
#define GEMM_SMEM_ELEMS (2 * (2 * SA_STAGE) + 2 * (2 * SB_STAGE))
#define GEMM_SMEM_BYTES (GEMM_SMEM_ELEMS * 2)   // 75776 bytes

__global__ __launch_bounds__(256)
void gemm_tc_kernel(const __nv_bfloat16* __restrict__ Ahg,
                    const __nv_bfloat16* __restrict__ Alg,
                    const __nv_bfloat16* __restrict__ Bhg,
                    const __nv_bfloat16* __restrict__ Blg,
                    float* __restrict__ Cm, int M, int N, int K)
{
    extern __shared__ __nv_bfloat16 dsm[];
    __nv_bfloat16* sAh = dsm;
    __nv_bfloat16* sAl = dsm + 2 * SA_STAGE;
    __nv_bfloat16* sBh = dsm + 4 * SA_STAGE;
    __nv_bfloat16* sBl = dsm + 4 * SA_STAGE + 2 * SB_STAGE;

    const int tid  = threadIdx.x;
    const int warp = tid >> 5;
    const int wm = warp & 3;
    const int wn = warp >> 2;
    const int bm = blockIdx.y * 128;
    const int bn = blockIdx.x * 128;

    wmma::fragment<wmma::accumulator, 16, 16, 16, float> acc[2][4];
#pragma unroll
    for (int mt = 0; mt < 2; mt++) {
#pragma unroll
        for (int nt = 0; nt < 4; nt++) {
            wmma::fill_fragment(acc[mt][nt], 0.0f);
        }
    }

    const int nk = K >> 5;   // BK = 32

    // prologue: stage 0
#pragma unroll
    for (int i = 0; i < 2; i++) {
        int gid = tid + i * 256;
        int arow = gid >> 2;
        int acol = (gid & 3) << 3;
        __pipeline_memcpy_async(&sAh[arow * GASTRIDE + acol],
                                &Ahg[(size_t)(bm + arow) * K + acol], 16);
        __pipeline_memcpy_async(&sAl[arow * GASTRIDE + acol],
                                &Alg[(size_t)(bm + arow) * K + acol], 16);
        int brow = gid >> 4;
        int bcol = (gid & 15) << 3;
        __pipeline_memcpy_async(&sBh[brow * GBSTRIDE + bcol],
                                &Bhg[(size_t)brow * N + bn + bcol], 16);
        __pipeline_memcpy_async(&sBl[brow * GBSTRIDE + bcol],
                                &Blg[(size_t)brow * N + bn + bcol], 16);
    }
    __pipeline_commit();

    for (int ks = 0; ks < nk; ks++) {
        __pipeline_wait_prior(0);
        __syncthreads();

        if (ks + 1 < nk) {
            const int k0 = (ks + 1) << 5;
            const int st = (ks + 1) & 1;
            const int ao = st * SA_STAGE;
            const int bo = st * SB_STAGE;
#pragma unroll
            for (int i = 0; i < 2; i++) {
                int gid = tid + i * 256;
                int arow = gid >> 2;
                int acol = (gid & 3) << 3;
                __pipeline_memcpy_async(&sAh[ao + arow * GASTRIDE + acol],
                                        &Ahg[(size_t)(bm + arow) * K + k0 + acol], 16);
                __pipeline_memcpy_async(&sAl[ao + arow * GASTRIDE + acol],
                                        &Alg[(size_t)(bm + arow) * K + k0 + acol], 16);
                int brow = gid >> 4;
                int bcol = (gid & 15) << 3;
                __pipeline_memcpy_async(&sBh[bo + brow * GBSTRIDE + bcol],
                                        &Bhg[(size_t)(k0 + brow) * N + bn + bcol], 16);
                __pipeline_memcpy_async(&sBl[bo + brow * GBSTRIDE + bcol],
                                        &Blg[(size_t)(k0 + brow) * N + bn + bcol], 16);
            }
            __pipeline_commit();
        }

        const int cur = ks & 1;
        const int ao = cur * SA_STAGE;
        const int bo = cur * SB_STAGE;

#pragma unroll
        for (int k16 = 0; k16 < 2; k16++) {
            const int kk = k16 << 4;
            wmma::fragment<wmma::matrix_a, 16, 16, 16, __nv_bfloat16, wmma::row_major> fa_h[2];
            wmma::fragment<wmma::matrix_a, 16, 16, 16, __nv_bfloat16, wmma::row_major> fa_l[2];
            wmma::fragment<wmma::matrix_b, 16, 16, 16, __nv_bfloat16, wmma::row_major> fb_h[4];
            wmma::fragment<wmma::matrix_b, 16, 16, 16, __nv_bfloat16, wmma::row_major> fb_l[4];
#pragma unroll
            for (int mt = 0; mt < 2; mt++) {
                const __nv_bfloat16* pa = &sAh[ao + (wm * 32 + mt * 16) * GASTRIDE + kk];
                wmma::load_matrix_sync(fa_h[mt], pa, GASTRIDE);
                const __nv_bfloat16* pl = &sAl[ao + (wm * 32 + mt * 16) * GASTRIDE + kk];
                wmma::load_matrix_sync(fa_l[mt], pl, GASTRIDE);
            }
#pragma unroll
            for (int nt = 0; nt < 4; nt++) {
                const __nv_bfloat16* pb = &sBh[bo + kk * GBSTRIDE + wn * 64 + nt * 16];
                wmma::load_matrix_sync(fb_h[nt], pb, GBSTRIDE);
                const __nv_bfloat16* pl = &sBl[bo + kk * GBSTRIDE + wn * 64 + nt * 16];
                wmma::load_matrix_sync(fb_l[nt], pl, GBSTRIDE);
            }
#pragma unroll
            for (int mt = 0; mt < 2; mt++) {
#pragma unroll
                for (int nt = 0; nt < 4; nt++) {
                    wmma::mma_sync(acc[mt][nt], fa_h[mt], fb_h[nt], acc[mt][nt]);
                    wmma::mma_sync(acc[mt][nt], fa_h[mt], fb_l[nt], acc[mt][nt]);
                    wmma::mma_sync(acc[mt][nt], fa_l[mt], fb_h[nt], acc[mt][nt]);
                }
            }
        }
    }

#pragma unroll
    for (int mt = 0; mt < 2; mt++) {
        int row0 = bm + wm * 32 + mt * 16;
#pragma unroll
        for (int nt = 0; nt < 4; nt++) {
            int col0 = bn + wn * 64 + nt * 16;
            float* dst = &Cm[(size_t)row0 * N + col0];
            wmma::store_matrix_sync(dst, acc[mt][nt], N, wmma::mem_row_major);
        }
    }
}

// ---------------------------------------------------------------------------
// RoPE in place on q and k slices of g_qkv.
// ---------------------------------------------------------------------------
__global__ __launch_bounds__(256)
void rope_kernel(float* __restrict__ qkv)
{
    int idx = blockIdx.x * blockDim.x + threadIdx.x;
    int d2 = idx & 31;
    int h  = (idx >> 5) & (NH - 1);
    int t  = (idx >> 9) & (TT - 1);
    int b  = idx >> 20;
    if (b >= BB) return;

    float invf = 1.0f / powf(10000.0f, (float)d2 / 32.0f);
    float ang  = (float)t * invf;
    float c = (float)cos((double)ang);
    float s = (float)sin((double)ang);

    size_t base = (size_t)(b * TT + t) * C3 + h * HD;
#pragma unroll
    for (int part = 0; part < 2; part++) {
        float* p = qkv + base + part * CC;
        float a0 = p[d2];
        float a1 = p[d2 + 32];
        p[d2]      = a0 * c - a1 * s;
        p[d2 + 32] = a1 * c + a0 * s;
    }
}

// ---------------------------------------------------------------------------
// Windowed causal attention, 2 queries/thread, conflict-free smem.
// ---------------------------------------------------------------------------
#define CHUNK 32
#define QKV_STRIDE 68
#define PS_STRIDE 36

__global__ __launch_bounds__(256)
void attn_kernel(const float* __restrict__ qkv,
                 __nv_bfloat16* __restrict__ ath,
                 __nv_bfloat16* __restrict__ atl)
{
    __shared__ float Qs[64 * QKV_STRIDE];
    __shared__ float Ks[CHUNK * QKV_STRIDE];
    __shared__ float Vs[CHUNK * QKV_STRIDE];
    __shared__ float Ps[64 * PS_STRIDE];

    const int tid = threadIdx.x;
    const int bid = blockIdx.x;
    const int qb = bid & 31;
    const int h  = (bid >> 5) & (NH - 1);
    const int b  = bid >> 9;
    const int q0 = qb * 64;
    const int sq = tid >> 3;
    const int kt = tid & 7;
    const float scale = 0.125f;

#pragma unroll
    for (int i = 0; i < 4; i++) {
        int f = tid + i * 256;
        int r = f >> 4;
        int c4 = (f & 15) << 2;
        const float* src = &qkv[(size_t)(b * TT + q0 + r) * C3 + h * HD + c4];
        float4 v = *reinterpret_cast<const float4*>(src);
        v.x *= scale;
        v.y *= scale;
        v.z *= scale;
        v.w *= scale;
        *reinterpret_cast<float4*>(&Qs[r * QKV_STRIDE + c4]) = v;
    }

    float m1 = -1e30f;
    float l1 = 0.f;
    float m2 = -1e30f;
    float l2 = 0.f;
    float o1[8];
    float o2[8];
#pragma unroll
    for (int i = 0; i < 8; i++) {
        o1[i] = 0.f;
        o2[i] = 0.f;
    }

    const int cstart = (q0 - WINDOW > 0) ? (q0 - WINDOW) : 0;
    const int do_sink = (cstart > 0) ? 1 : 0;
    const int nwin = (q0 + 64 - cstart) / CHUNK;
    const int nch = nwin + do_sink;

    for (int phase = 0; phase < nch; phase++) {
        const int c = (do_sink && phase == 0) ? 0 : cstart + (phase - do_sink) * CHUNK;

        __syncthreads();
#pragma unroll
        for (int i = 0; i < 2; i++) {
            int f = tid + i * 256;
            int r = f >> 4;
            int c4 = (f & 15) << 2;
            size_t rowbase = (size_t)(b * TT + c + r) * C3 + h * HD + c4;
            const float* srck = &qkv[rowbase + CC];
            *reinterpret_cast<float4*>(&Ks[r * QKV_STRIDE + c4]) =
                *reinterpret_cast<const float4*>(srck);
            const float* srcv = &qkv[rowbase + 2 * CC];
            *reinterpret_cast<float4*>(&Vs[r * QKV_STRIDE + c4]) =
                *reinterpret_cast<const float4*>(srcv);
        }
        __syncthreads();

        float s1[4];
        float s2[4];
#pragma unroll
        for (int i = 0; i < 4; i++) {
            s1[i] = 0.f;
            s2[i] = 0.f;
        }
#pragma unroll
        for (int d4 = 0; d4 < 16; d4++) {
            float4 q1 = *reinterpret_cast<const float4*>(&Qs[sq * QKV_STRIDE + d4 * 4]);
            float4 q2 = *reinterpret_cast<const float4*>(&Qs[(sq + 32) * QKV_STRIDE + d4 * 4]);
#pragma unroll
            for (int kki = 0; kki < 4; kki++) {
                const float* kp = &Ks[(kt + kki * 8) * QKV_STRIDE + d4 * 4];
                float4 kv = *reinterpret_cast<const float4*>(kp);
                s1[kki] += q1.x * kv.x + q1.y * kv.y + q1.z * kv.z + q1.w * kv.w;
                s2[kki] += q2.x * kv.x + q2.y * kv.y + q2.z * kv.z + q2.w * kv.w;
            }
        }
        const int qq1 = q0 + sq;
        const int qq2 = q0 + sq + 32;
        float mc1 = -1e30f;
        float mc2 = -1e30f;
#pragma unroll
        for (int kki = 0; kki < 4; kki++) {
            int j = c + kt + kki * 8;
            bool a1 = (j <= qq1) && (((qq1 - j) < WINDOW) || (j < SINK));
            if (!a1) s1[kki] = -1e30f;
            mc1 = fmaxf(mc1, s1[kki]);
            bool a2 = (j <= qq2) && (((qq2 - j) < WINDOW) || (j < SINK));
            if (!a2) s2[kki] = -1e30f;
            mc2 = fmaxf(mc2, s2[kki]);
        }
        mc1 = fmaxf(mc1, __shfl_xor_sync(0xffffffffu, mc1, 1));
        mc1 = fmaxf(mc1, __shfl_xor_sync(0xffffffffu, mc1, 2));
        mc1 = fmaxf(mc1, __shfl_xor_sync(0xffffffffu, mc1, 4));
        mc2 = fmaxf(mc2, __shfl_xor_sync(0xffffffffu, mc2, 1));
        mc2 = fmaxf(mc2, __shfl_xor_sync(0xffffffffu, mc2, 2));
        mc2 = fmaxf(mc2, __shfl_xor_sync(0xffffffffu, mc2, 4));
        float mn1 = fmaxf(m1, mc1);
        float mn2 = fmaxf(m2, mc2);
        float alpha1 = expf(m1 - mn1);
        float alpha2 = expf(m2 - mn2);

        float lc1 = 0.f;
        float lc2 = 0.f;
#pragma unroll
        for (int kki = 0; kki < 4; kki++) {
            float p1 = expf(s1[kki] - mn1);
            lc1 += p1;
            Ps[sq * PS_STRIDE + kt + kki * 8] = p1;
            float p2 = expf(s2[kki] - mn2);
            lc2 += p2;
            Ps[(sq + 32) * PS_STRIDE + kt + kki * 8] = p2;
        }
        lc1 += __shfl_xor_sync(0xffffffffu, lc1, 1);
        lc1 += __shfl_xor_sync(0xffffffffu, lc1, 2);
        lc1 += __shfl_xor_sync(0xffffffffu, lc1, 4);
        lc2 += __shfl_xor_sync(0xffffffffu, lc2, 1);
        lc2 += __shfl_xor_sync(0xffffffffu, lc2, 2);
        lc2 += __shfl_xor_sync(0xffffffffu, lc2, 4);
        l1 = l1 * alpha1 + lc1;
        l2 = l2 * alpha2 + lc2;
        m1 = mn1;
        m2 = mn2;

        __syncthreads();

#pragma unroll
        for (int i = 0; i < 8; i++) {
            o1[i] *= alpha1;
            o2[i] *= alpha2;
        }
        for (int j = 0; j < CHUNK; j++) {
            float p1 = Ps[sq * PS_STRIDE + j];
            float p2 = Ps[(sq + 32) * PS_STRIDE + j];
            const float* vpa = &Vs[j * QKV_STRIDE + kt * 4];
            float4 va = *reinterpret_cast<const float4*>(vpa);
            const float* vpb = &Vs[j * QKV_STRIDE + kt * 4 + 32];
            float4 vb = *reinterpret_cast<const float4*>(vpb);
            o1[0] += p1 * va.x;
            o1[1] += p1 * va.y;
            o1[2] += p1 * va.z;
            o1[3] += p1 * va.w;
            o1[4] += p1 * vb.x;
            o1[5] += p1 * vb.y;
            o1[6] += p1 * vb.z;
            o1[7] += p1 * vb.w;
            o2[0] += p2 * va.x;
            o2[1] += p2 * va.y;
            o2[2] += p2 * va.z;
            o2[3] += p2 * va.w;
            o2[4] += p2 * vb.x;
            o2[5] += p2 * vb.y;
            o2[6] += p2 * vb.z;
            o2[7] += p2 * vb.w;
        }
    }

    float inv1 = 1.0f / l1;
    float inv2 = 1.0f / l2;
#pragma unroll
    for (int qi = 0; qi < 2; qi++) {
        float inv = (qi == 0) ? inv1 : inv2;
        const float* oo = (qi == 0) ? o1 : o2;
        size_t rowbase = (size_t)(b * TT + q0 + sq + qi * 32) * CC + h * HD;
#pragma unroll
        for (int half = 0; half < 2; half++) {
            unsigned short hs[4];
            unsigned short ls[4];
#pragma unroll
            for (int e = 0; e < 4; e++) {
                float val = oo[half * 4 + e] * inv;
                __nv_bfloat16 hb = __float2bfloat16(val);
                float r = val - __bfloat162float(hb);
                __nv_bfloat16 lb = __float2bfloat16(r);
                hs[e] = __bfloat16_as_ushort(hb);
                ls[e] = __bfloat16_as_ushort(lb);
            }
            uint2 hp;
            hp.x = (uint32_t)hs[0] | ((uint32_t)hs[1] << 16);
            hp.y = (uint32_t)hs[2] | ((uint32_t)hs[3] << 16);
            uint2 lp;
            lp.x = (uint32_t)ls[0] | ((uint32_t)ls[1] << 16);
            lp.y = (uint32_t)ls[2] | ((uint32_t)ls[3] << 16);
            size_t off = rowbase + kt * 4 + half * 32;
            *reinterpret_cast<uint2*>(&ath[off]) = hp;
            *reinterpret_cast<uint2*>(&atl[off]) = lp;
        }
    }
}

// ---------------------------------------------------------------------------
extern "C" void kernel_launch(void* const* d_in, const int* in_sizes, int n_in,
                              void* d_out, int out_size)
{
    const float* x = nullptr;
    const float* w_attn = nullptr;
    const float* w_proj = nullptr;
    for (int i = 0; i < n_in; i++) {
        if (in_sizes[i] == BB * TT * CC)      x      = (const float*)d_in[i];
        else if (in_sizes[i] == CC * C3)      w_attn = (const float*)d_in[i];
        else if (in_sizes[i] == CC * CC)      w_proj = (const float*)d_in[i];
    }
    if (!x || !w_attn || !w_proj) {
        x      = (const float*)d_in[0];
        w_attn = (const float*)d_in[1];
        w_proj = (const float*)d_in[2];
    }
    float* out = (float*)d_out;

    void* p;
    cudaGetSymbolAddress(&p, g_qkv);
    float* qkv = (float*)p;
    cudaGetSymbolAddress(&p, g_xh);
    __nv_bfloat16* xh = (__nv_bfloat16*)p;
    cudaGetSymbolAddress(&p, g_xl);
    __nv_bfloat16* xl = (__nv_bfloat16*)p;
    cudaGetSymbolAddress(&p, g_wah);
    __nv_bfloat16* wah = (__nv_bfloat16*)p;
    cudaGetSymbolAddress(&p, g_wal);
    __nv_bfloat16* wal = (__nv_bfloat16*)p;
    cudaGetSymbolAddress(&p, g_wph);
    __nv_bfloat16* wph = (__nv_bfloat16*)p;
    cudaGetSymbolAddress(&p, g_wpl);
    __nv_bfloat16* wpl = (__nv_bfloat16*)p;
    cudaGetSymbolAddress(&p, g_ath);
    __nv_bfloat16* ath = (__nv_bfloat16*)p;
    cudaGetSymbolAddress(&p, g_atl);
    __nv_bfloat16* atl = (__nv_bfloat16*)p;

    // allow >48KB dynamic smem for the GEMM (host-side attribute, not an alloc)
    cudaFuncSetAttribute(gemm_tc_kernel,
                         cudaFuncAttributeMaxDynamicSharedMemorySize,
                         GEMM_SMEM_BYTES);

    // splits of inputs
    {
        int n4 = (MROWS * CC) / 4;
        split_kernel<<<(n4 + 255) / 256, 256>>>(x, xh, xl, n4);
    }
    {
        int n4 = (CC * C3) / 4;
        split_kernel<<<(n4 + 255) / 256, 256>>>(w_attn, wah, wal, n4);
    }
    {
        int n4 = (CC * CC) / 4;
        split_kernel<<<(n4 + 255) / 256, 256>>>(w_proj, wph, wpl, n4);
    }
    // qkv = x @ w_attn
    {
        dim3 grid(C3 / 128, MROWS / 128);
        gemm_tc_kernel<<<grid, 256, GEMM_SMEM_BYTES>>>(xh, xl, wah, wal, qkv, MROWS, C3, CC);
    }
    // RoPE
    {
        int total = BB * TT * NH * 32;
        rope_kernel<<<total / 256, 256>>>(qkv);
    }
    // attention (writes bf16 hi/lo directly)
    {
        int grid = BB * NH * (TT / 64);
        attn_kernel<<<grid, 256>>>(qkv, ath, atl);
    }
    // out = att @ w_proj
    {
        dim3 grid(CC / 128, MROWS / 128);
        gemm_tc_kernel<<<grid, 256, GEMM_SMEM_BYTES>>>(ath, atl, wph, wpl, out, MROWS, CC, CC);
    }
}

// round 13
// speedup vs baseline: 3.2633x; 1.1218x over previous
#include <cuda_runtime.h>
#include <cuda_bf16.h>
#include <cuda_pipeline.h>
#include <mma.h>
#include <math.h>

using namespace nvcuda;

// Problem constants
#define BB 2
#define TT 2048
#define CC 1024
#define NH 16
#define HD 64
#define WINDOW 256
#define SINK 4
#define MROWS (BB*TT)
#define C3 (3*CC)

// Scratch (device globals: no allocation allowed)
__device__ float g_qkv[MROWS * C3];
__device__ __nv_bfloat16 g_xh[MROWS * CC];
__device__ __nv_bfloat16 g_xl[MROWS * CC];
__device__ __nv_bfloat16 g_wah[CC * C3];
__device__ __nv_bfloat16 g_wal[CC * C3];
__device__ __nv_bfloat16 g_wph[CC * CC];
__device__ __nv_bfloat16 g_wpl[CC * CC];
__device__ __nv_bfloat16 g_ath[MROWS * CC];
__device__ __nv_bfloat16 g_atl[MROWS * CC];

__device__ __forceinline__ void split2f(float x, unsigned short& h, unsigned short& l) {
    __nv_bfloat16 hb = __float2bfloat16(x);
    float r = x - __bfloat162float(hb);
    __nv_bfloat16 lb = __float2bfloat16(r);
    h = __bfloat16_as_ushort(hb);
    l = __bfloat16_as_ushort(lb);
}

// ---------------------------------------------------------------------------
// Split fp32 -> bf16 hi + bf16 lo (residual). Vectorized float4 per thread.
// ---------------------------------------------------------------------------
__global__ __launch_bounds__(256)
void split_kernel(const float* __restrict__ src,
                  __nv_bfloat16* __restrict__ dh,
                  __nv_bfloat16* __restrict__ dl, int n4)
{
    int idx = blockIdx.x * blockDim.x + threadIdx.x;
    if (idx >= n4) return;
    float4 v = reinterpret_cast<const float4*>(src)[idx];
    float vals[4];
    vals[0] = v.x;
    vals[1] = v.y;
    vals[2] = v.z;
    vals[3] = v.w;
    unsigned short hs[4];
    unsigned short ls[4];
#pragma unroll
    for (int i = 0; i < 4; i++) {
        split2f(vals[i], hs[i], ls[i]);
    }
    uint2 hp;
    hp.x = (uint32_t)hs[0] | ((uint32_t)hs[1] << 16);
    hp.y = (uint32_t)hs[2] | ((uint32_t)hs[3] << 16);
    uint2 lp;
    lp.x = (uint32_t)ls[0] | ((uint32_t)ls[1] << 16);
    lp.y = (uint32_t)ls[2] | ((uint32_t)ls[3] << 16);
    reinterpret_cast<uint2*>(dh)[idx] = hp;
    reinterpret_cast<uint2*>(dl)[idx] = lp;
}

// ===========================================================================
// Double-buffered split-bf16 GEMM (unchanged from R12 best).
// ===========================================================================
#define GASTRIDE 40
#define GBSTRIDE 136
#define SA_STAGE (128 * GASTRIDE)
#define SB_STAGE (32 * GBSTRIDE)
#define GEMM_SMEM_ELEMS (2 * (2 * SA_STAGE) + 2 * (2 * SB_STAGE))
#define GEMM_SMEM_BYTES (GEMM_SMEM_ELEMS * 2)

__global__ __launch_bounds__(256)
void gemm_tc_kernel(const __nv_bfloat16* __restrict__ Ahg,
                    const __nv_bfloat16* __restrict__ Alg,
                    const __nv_bfloat16* __restrict__ Bhg,
                    const __nv_bfloat16* __restrict__ Blg,
                    float* __restrict__ Cm, int M, int N, int K)
{
    extern __shared__ __nv_bfloat16 dsm[];
    __nv_bfloat16* sAh = dsm;
    __nv_bfloat16* sAl = dsm + 2 * SA_STAGE;
    __nv_bfloat16* sBh = dsm + 4 * SA_STAGE;
    __nv_bfloat16* sBl = dsm + 4 * SA_STAGE + 2 * SB_STAGE;

    const int tid  = threadIdx.x;
    const int warp = tid >> 5;
    const int wm = warp & 3;
    const int wn = warp >> 2;
    const int bm = blockIdx.y * 128;
    const int bn = blockIdx.x * 128;

    wmma::fragment<wmma::accumulator, 16, 16, 16, float> acc[2][4];
#pragma unroll
    for (int mt = 0; mt < 2; mt++) {
#pragma unroll
        for (int nt = 0; nt < 4; nt++) {
            wmma::fill_fragment(acc[mt][nt], 0.0f);
        }
    }

    const int nk = K >> 5;

#pragma unroll
    for (int i = 0; i < 2; i++) {
        int gid = tid + i * 256;
        int arow = gid >> 2;
        int acol = (gid & 3) << 3;
        __pipeline_memcpy_async(&sAh[arow * GASTRIDE + acol],
                                &Ahg[(size_t)(bm + arow) * K + acol], 16);
        __pipeline_memcpy_async(&sAl[arow * GASTRIDE + acol],
                                &Alg[(size_t)(bm + arow) * K + acol], 16);
        int brow = gid >> 4;
        int bcol = (gid & 15) << 3;
        __pipeline_memcpy_async(&sBh[brow * GBSTRIDE + bcol],
                                &Bhg[(size_t)brow * N + bn + bcol], 16);
        __pipeline_memcpy_async(&sBl[brow * GBSTRIDE + bcol],
                                &Blg[(size_t)brow * N + bn + bcol], 16);
    }
    __pipeline_commit();

    for (int ks = 0; ks < nk; ks++) {
        __pipeline_wait_prior(0);
        __syncthreads();

        if (ks + 1 < nk) {
            const int k0 = (ks + 1) << 5;
            const int st = (ks + 1) & 1;
            const int ao = st * SA_STAGE;
            const int bo = st * SB_STAGE;
#pragma unroll
            for (int i = 0; i < 2; i++) {
                int gid = tid + i * 256;
                int arow = gid >> 2;
                int acol = (gid & 3) << 3;
                __pipeline_memcpy_async(&sAh[ao + arow * GASTRIDE + acol],
                                        &Ahg[(size_t)(bm + arow) * K + k0 + acol], 16);
                __pipeline_memcpy_async(&sAl[ao + arow * GASTRIDE + acol],
                                        &Alg[(size_t)(bm + arow) * K + k0 + acol], 16);
                int brow = gid >> 4;
                int bcol = (gid & 15) << 3;
                __pipeline_memcpy_async(&sBh[bo + brow * GBSTRIDE + bcol],
                                        &Bhg[(size_t)(k0 + brow) * N + bn + bcol], 16);
                __pipeline_memcpy_async(&sBl[bo + brow * GBSTRIDE + bcol],
                                        &Blg[(size_t)(k0 + brow) * N + bn + bcol], 16);
            }
            __pipeline_commit();
        }

        const int cur = ks & 1;
        const int ao = cur * SA_STAGE;
        const int bo = cur * SB_STAGE;

#pragma unroll
        for (int k16 = 0; k16 < 2; k16++) {
            const int kk = k16 << 4;
            wmma::fragment<wmma::matrix_a, 16, 16, 16, __nv_bfloat16, wmma::row_major> fa_h[2];
            wmma::fragment<wmma::matrix_a, 16, 16, 16, __nv_bfloat16, wmma::row_major> fa_l[2];
            wmma::fragment<wmma::matrix_b, 16, 16, 16, __nv_bfloat16, wmma::row_major> fb_h[4];
            wmma::fragment<wmma::matrix_b, 16, 16, 16, __nv_bfloat16, wmma::row_major> fb_l[4];
#pragma unroll
            for (int mt = 0; mt < 2; mt++) {
                const __nv_bfloat16* pa = &sAh[ao + (wm * 32 + mt * 16) * GASTRIDE + kk];
                wmma::load_matrix_sync(fa_h[mt], pa, GASTRIDE);
                const __nv_bfloat16* pl = &sAl[ao + (wm * 32 + mt * 16) * GASTRIDE + kk];
                wmma::load_matrix_sync(fa_l[mt], pl, GASTRIDE);
            }
#pragma unroll
            for (int nt = 0; nt < 4; nt++) {
                const __nv_bfloat16* pb = &sBh[bo + kk * GBSTRIDE + wn * 64 + nt * 16];
                wmma::load_matrix_sync(fb_h[nt], pb, GBSTRIDE);
                const __nv_bfloat16* pl = &sBl[bo + kk * GBSTRIDE + wn * 64 + nt * 16];
                wmma::load_matrix_sync(fb_l[nt], pl, GBSTRIDE);
            }
#pragma unroll
            for (int mt = 0; mt < 2; mt++) {
#pragma unroll
                for (int nt = 0; nt < 4; nt++) {
                    wmma::mma_sync(acc[mt][nt], fa_h[mt], fb_h[nt], acc[mt][nt]);
                    wmma::mma_sync(acc[mt][nt], fa_h[mt], fb_l[nt], acc[mt][nt]);
                    wmma::mma_sync(acc[mt][nt], fa_l[mt], fb_h[nt], acc[mt][nt]);
                }
            }
        }
    }

#pragma unroll
    for (int mt = 0; mt < 2; mt++) {
        int row0 = bm + wm * 32 + mt * 16;
#pragma unroll
        for (int nt = 0; nt < 4; nt++) {
            int col0 = bn + wn * 64 + nt * 16;
            float* dst = &Cm[(size_t)row0 * N + col0];
            wmma::store_matrix_sync(dst, acc[mt][nt], N, wmma::mem_row_major);
        }
    }
}

// ---------------------------------------------------------------------------
// RoPE in place on q and k slices of g_qkv.
// ---------------------------------------------------------------------------
__global__ __launch_bounds__(256)
void rope_kernel(float* __restrict__ qkv)
{
    int idx = blockIdx.x * blockDim.x + threadIdx.x;
    int d2 = idx & 31;
    int h  = (idx >> 5) & (NH - 1);
    int t  = (idx >> 9) & (TT - 1);
    int b  = idx >> 20;
    if (b >= BB) return;

    float invf = 1.0f / powf(10000.0f, (float)d2 / 32.0f);
    float ang  = (float)t * invf;
    float c = (float)cos((double)ang);
    float s = (float)sin((double)ang);

    size_t base = (size_t)(b * TT + t) * C3 + h * HD;
#pragma unroll
    for (int part = 0; part < 2; part++) {
        float* p = qkv + base + part * CC;
        float a0 = p[d2];
        float a1 = p[d2 + 32];
        p[d2]      = a0 * c - a1 * s;
        p[d2 + 32] = a1 * c + a0 * s;
    }
}

// ---------------------------------------------------------------------------
// Tensor-core windowed attention (split-bf16 3-pass for QK^T and PV).
// Block = 64 queries. Per 32-key chunk:
//   scores S[64x32] via wmma (8 warps, 1 frag each), scalar online softmax,
//   P split to bf16, PV via wmma with O accumulator staged in smem fp32.
// ---------------------------------------------------------------------------
#define CHUNK 32
#define AQ_STR 72
#define AS_STR 36
#define AP_STR 40
#define AO_STR 72

#define OFF_QH 0
#define OFF_QL 9216
#define OFF_KH 18432
#define OFF_KL 23040
#define OFF_VH 27648
#define OFF_VL 32256
#define OFF_S  36864
#define OFF_PH 46080
#define OFF_PL 51200
#define OFF_O  56320
#define ATTN_SMEM_BYTES 74752

__global__ __launch_bounds__(256)
void attn_kernel(const float* __restrict__ qkv,
                 __nv_bfloat16* __restrict__ ath,
                 __nv_bfloat16* __restrict__ atl)
{
    extern __shared__ char smraw[];
    __nv_bfloat16* Qh = reinterpret_cast<__nv_bfloat16*>(smraw + OFF_QH);
    __nv_bfloat16* Ql = reinterpret_cast<__nv_bfloat16*>(smraw + OFF_QL);
    __nv_bfloat16* Kh = reinterpret_cast<__nv_bfloat16*>(smraw + OFF_KH);
    __nv_bfloat16* Kl = reinterpret_cast<__nv_bfloat16*>(smraw + OFF_KL);
    __nv_bfloat16* Vh = reinterpret_cast<__nv_bfloat16*>(smraw + OFF_VH);
    __nv_bfloat16* Vl = reinterpret_cast<__nv_bfloat16*>(smraw + OFF_VL);
    float* Ssm = reinterpret_cast<float*>(smraw + OFF_S);
    __nv_bfloat16* Ph = reinterpret_cast<__nv_bfloat16*>(smraw + OFF_PH);
    __nv_bfloat16* Pl = reinterpret_cast<__nv_bfloat16*>(smraw + OFF_PL);
    float* Osm = reinterpret_cast<float*>(smraw + OFF_O);

    const int tid = threadIdx.x;
    const int warp = tid >> 5;
    const int bid = blockIdx.x;
    const int qb = bid & 31;
    const int h  = (bid >> 5) & (NH - 1);
    const int b  = bid >> 9;
    const int q0 = qb * 64;
    const int sq = tid >> 3;          // 0..31 (query row; also row sq+32)
    const int kt = tid & 7;           // 0..7
    const float scale = 0.125f;

    // Q load + scale + split: 64x64 fp32 -> Qh/Ql
#pragma unroll
    for (int i = 0; i < 4; i++) {
        int f = tid + i * 256;
        int r = f >> 4;
        int c4 = (f & 15) << 2;
        const float* src = &qkv[(size_t)(b * TT + q0 + r) * C3 + h * HD + c4];
        float4 v = *reinterpret_cast<const float4*>(src);
        unsigned short hs[4];
        unsigned short ls[4];
        split2f(v.x * scale, hs[0], ls[0]);
        split2f(v.y * scale, hs[1], ls[1]);
        split2f(v.z * scale, hs[2], ls[2]);
        split2f(v.w * scale, hs[3], ls[3]);
        uint2 hp;
        hp.x = (uint32_t)hs[0] | ((uint32_t)hs[1] << 16);
        hp.y = (uint32_t)hs[2] | ((uint32_t)hs[3] << 16);
        uint2 lp;
        lp.x = (uint32_t)ls[0] | ((uint32_t)ls[1] << 16);
        lp.y = (uint32_t)ls[2] | ((uint32_t)ls[3] << 16);
        *reinterpret_cast<uint2*>(&Qh[r * AQ_STR + c4]) = hp;
        *reinterpret_cast<uint2*>(&Ql[r * AQ_STR + c4]) = lp;
    }
    // zero O: 64*72 = 4608 floats = 18 per thread
#pragma unroll
    for (int i = 0; i < 18; i++) {
        Osm[tid + i * 256] = 0.f;
    }

    float m1 = -1e30f;
    float l1 = 0.f;
    float m2 = -1e30f;
    float l2 = 0.f;

    const int cstart = (q0 - WINDOW > 0) ? (q0 - WINDOW) : 0;
    const int do_sink = (cstart > 0) ? 1 : 0;
    const int nwin = (q0 + 64 - cstart) / CHUNK;
    const int nch = nwin + do_sink;

    for (int phase = 0; phase < nch; phase++) {
        const int c = (do_sink && phase == 0) ? 0 : cstart + (phase - do_sink) * CHUNK;

        __syncthreads();   // V/K/S/P reuse from previous phase (Q/O init on phase 0)
        // K/V chunk load + split: 32x64 each, 2 float4 per thread per tensor
#pragma unroll
        for (int i = 0; i < 2; i++) {
            int f = tid + i * 256;
            int r = f >> 4;
            int c4 = (f & 15) << 2;
            size_t rowbase = (size_t)(b * TT + c + r) * C3 + h * HD + c4;
            float4 kv = *reinterpret_cast<const float4*>(&qkv[rowbase + CC]);
            float4 vv = *reinterpret_cast<const float4*>(&qkv[rowbase + 2 * CC]);
            unsigned short hs[4];
            unsigned short ls[4];
            split2f(kv.x, hs[0], ls[0]);
            split2f(kv.y, hs[1], ls[1]);
            split2f(kv.z, hs[2], ls[2]);
            split2f(kv.w, hs[3], ls[3]);
            uint2 hp;
            hp.x = (uint32_t)hs[0] | ((uint32_t)hs[1] << 16);
            hp.y = (uint32_t)hs[2] | ((uint32_t)hs[3] << 16);
            uint2 lp;
            lp.x = (uint32_t)ls[0] | ((uint32_t)ls[1] << 16);
            lp.y = (uint32_t)ls[2] | ((uint32_t)ls[3] << 16);
            *reinterpret_cast<uint2*>(&Kh[r * AQ_STR + c4]) = hp;
            *reinterpret_cast<uint2*>(&Kl[r * AQ_STR + c4]) = lp;
            split2f(vv.x, hs[0], ls[0]);
            split2f(vv.y, hs[1], ls[1]);
            split2f(vv.z, hs[2], ls[2]);
            split2f(vv.w, hs[3], ls[3]);
            hp.x = (uint32_t)hs[0] | ((uint32_t)hs[1] << 16);
            hp.y = (uint32_t)hs[2] | ((uint32_t)hs[3] << 16);
            lp.x = (uint32_t)ls[0] | ((uint32_t)ls[1] << 16);
            lp.y = (uint32_t)ls[2] | ((uint32_t)ls[3] << 16);
            *reinterpret_cast<uint2*>(&Vh[r * AQ_STR + c4]) = hp;
            *reinterpret_cast<uint2*>(&Vl[r * AQ_STR + c4]) = lp;
        }
        __syncthreads();

        // ---- scores via wmma: warp computes frag (qr, kc) of S[64x32] ----
        {
            const int qr = (warp & 3) * 16;
            const int kc = (warp >> 2) * 16;
            wmma::fragment<wmma::accumulator, 16, 16, 16, float> acc_s;
            wmma::fill_fragment(acc_s, 0.0f);
#pragma unroll
            for (int d4 = 0; d4 < 4; d4++) {
                wmma::fragment<wmma::matrix_a, 16, 16, 16, __nv_bfloat16, wmma::row_major> fa_h;
                wmma::fragment<wmma::matrix_a, 16, 16, 16, __nv_bfloat16, wmma::row_major> fa_l;
                wmma::fragment<wmma::matrix_b, 16, 16, 16, __nv_bfloat16, wmma::col_major> fb_h;
                wmma::fragment<wmma::matrix_b, 16, 16, 16, __nv_bfloat16, wmma::col_major> fb_l;
                wmma::load_matrix_sync(fa_h, &Qh[qr * AQ_STR + d4 * 16], AQ_STR);
                wmma::load_matrix_sync(fa_l, &Ql[qr * AQ_STR + d4 * 16], AQ_STR);
                wmma::load_matrix_sync(fb_h, &Kh[kc * AQ_STR + d4 * 16], AQ_STR);
                wmma::load_matrix_sync(fb_l, &Kl[kc * AQ_STR + d4 * 16], AQ_STR);
                wmma::mma_sync(acc_s, fa_h, fb_h, acc_s);
                wmma::mma_sync(acc_s, fa_h, fb_l, acc_s);
                wmma::mma_sync(acc_s, fa_l, fb_h, acc_s);
            }
            wmma::store_matrix_sync(&Ssm[qr * AS_STR + kc], acc_s, AS_STR, wmma::mem_row_major);
        }
        __syncthreads();

        // ---- scalar online softmax (reads S, writes Ph/Pl, rescales O) ----
        {
            float s1[4];
            float s2[4];
#pragma unroll
            for (int kki = 0; kki < 4; kki++) {
                s1[kki] = Ssm[sq * AS_STR + kt + kki * 8];
                s2[kki] = Ssm[(sq + 32) * AS_STR + kt + kki * 8];
            }
            const int qq1 = q0 + sq;
            const int qq2 = q0 + sq + 32;
            float mc1 = -1e30f;
            float mc2 = -1e30f;
#pragma unroll
            for (int kki = 0; kki < 4; kki++) {
                int j = c + kt + kki * 8;
                bool a1 = (j <= qq1) && (((qq1 - j) < WINDOW) || (j < SINK));
                if (!a1) s1[kki] = -1e30f;
                mc1 = fmaxf(mc1, s1[kki]);
                bool a2 = (j <= qq2) && (((qq2 - j) < WINDOW) || (j < SINK));
                if (!a2) s2[kki] = -1e30f;
                mc2 = fmaxf(mc2, s2[kki]);
            }
            mc1 = fmaxf(mc1, __shfl_xor_sync(0xffffffffu, mc1, 1));
            mc1 = fmaxf(mc1, __shfl_xor_sync(0xffffffffu, mc1, 2));
            mc1 = fmaxf(mc1, __shfl_xor_sync(0xffffffffu, mc1, 4));
            mc2 = fmaxf(mc2, __shfl_xor_sync(0xffffffffu, mc2, 1));
            mc2 = fmaxf(mc2, __shfl_xor_sync(0xffffffffu, mc2, 2));
            mc2 = fmaxf(mc2, __shfl_xor_sync(0xffffffffu, mc2, 4));
            float mn1 = fmaxf(m1, mc1);
            float mn2 = fmaxf(m2, mc2);
            float alpha1 = expf(m1 - mn1);
            float alpha2 = expf(m2 - mn2);

            float lc1 = 0.f;
            float lc2 = 0.f;
#pragma unroll
            for (int kki = 0; kki < 4; kki++) {
                int j = kt + kki * 8;
                float p1 = expf(s1[kki] - mn1);
                lc1 += p1;
                unsigned short hh;
                unsigned short ll;
                split2f(p1, hh, ll);
                Ph[sq * AP_STR + j] = __ushort_as_bfloat16(hh);
                Pl[sq * AP_STR + j] = __ushort_as_bfloat16(ll);
                float p2 = expf(s2[kki] - mn2);
                lc2 += p2;
                split2f(p2, hh, ll);
                Ph[(sq + 32) * AP_STR + j] = __ushort_as_bfloat16(hh);
                Pl[(sq + 32) * AP_STR + j] = __ushort_as_bfloat16(ll);
            }
            lc1 += __shfl_xor_sync(0xffffffffu, lc1, 1);
            lc1 += __shfl_xor_sync(0xffffffffu, lc1, 2);
            lc1 += __shfl_xor_sync(0xffffffffu, lc1, 4);
            lc2 += __shfl_xor_sync(0xffffffffu, lc2, 1);
            lc2 += __shfl_xor_sync(0xffffffffu, lc2, 2);
            lc2 += __shfl_xor_sync(0xffffffffu, lc2, 4);
            l1 = l1 * alpha1 + lc1;
            l2 = l2 * alpha2 + lc2;
            m1 = mn1;
            m2 = mn2;

            // rescale O rows sq (alpha1) and sq+32 (alpha2), dims kt*4..+3 and +32
#pragma unroll
            for (int e = 0; e < 4; e++) {
                Osm[sq * AO_STR + kt * 4 + e] *= alpha1;
                Osm[sq * AO_STR + kt * 4 + 32 + e] *= alpha1;
                Osm[(sq + 32) * AO_STR + kt * 4 + e] *= alpha2;
                Osm[(sq + 32) * AO_STR + kt * 4 + 32 + e] *= alpha2;
            }
        }
        __syncthreads();

        // ---- PV via wmma: warp covers rows (warp&3)*16, cols (warp>>2)*32 ----
        {
            const int qr = (warp & 3) * 16;
            const int vc0 = (warp >> 2) * 32;
            wmma::fragment<wmma::matrix_a, 16, 16, 16, __nv_bfloat16, wmma::row_major> pa_h[2];
            wmma::fragment<wmma::matrix_a, 16, 16, 16, __nv_bfloat16, wmma::row_major> pa_l[2];
#pragma unroll
            for (int k16 = 0; k16 < 2; k16++) {
                wmma::load_matrix_sync(pa_h[k16], &Ph[qr * AP_STR + k16 * 16], AP_STR);
                wmma::load_matrix_sync(pa_l[k16], &Pl[qr * AP_STR + k16 * 16], AP_STR);
            }
#pragma unroll
            for (int cf = 0; cf < 2; cf++) {
                const int vc = vc0 + cf * 16;
                wmma::fragment<wmma::accumulator, 16, 16, 16, float> acc_o;
                wmma::load_matrix_sync(acc_o, &Osm[qr * AO_STR + vc], AO_STR, wmma::mem_row_major);
#pragma unroll
                for (int k16 = 0; k16 < 2; k16++) {
                    wmma::fragment<wmma::matrix_b, 16, 16, 16, __nv_bfloat16, wmma::row_major> vb_h;
                    wmma::fragment<wmma::matrix_b, 16, 16, 16, __nv_bfloat16, wmma::row_major> vb_l;
                    wmma::load_matrix_sync(vb_h, &Vh[(k16 * 16) * AQ_STR + vc], AQ_STR);
                    wmma::load_matrix_sync(vb_l, &Vl[(k16 * 16) * AQ_STR + vc], AQ_STR);
                    wmma::mma_sync(acc_o, pa_h[k16], vb_h, acc_o);
                    wmma::mma_sync(acc_o, pa_h[k16], vb_l, acc_o);
                    wmma::mma_sync(acc_o, pa_l[k16], vb_h, acc_o);
                }
                wmma::store_matrix_sync(&Osm[qr * AO_STR + vc], acc_o, AO_STR, wmma::mem_row_major);
            }
        }
    }

    __syncthreads();

    // epilogue: normalize O rows, split to bf16 hi/lo, write global
    float inv1 = 1.0f / l1;
    float inv2 = 1.0f / l2;
#pragma unroll
    for (int qi = 0; qi < 2; qi++) {
        float inv = (qi == 0) ? inv1 : inv2;
        int row = sq + qi * 32;
        size_t rowbase = (size_t)(b * TT + q0 + row) * CC + h * HD;
#pragma unroll
        for (int half = 0; half < 2; half++) {
            unsigned short hs[4];
            unsigned short ls[4];
#pragma unroll
            for (int e = 0; e < 4; e++) {
                float val = Osm[row * AO_STR + kt * 4 + half * 32 + e] * inv;
                split2f(val, hs[e], ls[e]);
            }
            uint2 hp;
            hp.x = (uint32_t)hs[0] | ((uint32_t)hs[1] << 16);
            hp.y = (uint32_t)hs[2] | ((uint32_t)hs[3] << 16);
            uint2 lp;
            lp.x = (uint32_t)ls[0] | ((uint32_t)ls[1] << 16);
            lp.y = (uint32_t)ls[2] | ((uint32_t)ls[3] << 16);
            size_t off = rowbase + kt * 4 + half * 32;
            *reinterpret_cast<uint2*>(&ath[off]) = hp;
            *reinterpret_cast<uint2*>(&atl[off]) = lp;
        }
    }
}

// ---------------------------------------------------------------------------
extern "C" void kernel_launch(void* const* d_in, const int* in_sizes, int n_in,
                              void* d_out, int out_size)
{
    const float* x = nullptr;
    const float* w_attn = nullptr;
    const float* w_proj = nullptr;
    for (int i = 0; i < n_in; i++) {
        if (in_sizes[i] == BB * TT * CC)      x      = (const float*)d_in[i];
        else if (in_sizes[i] == CC * C3)      w_attn = (const float*)d_in[i];
        else if (in_sizes[i] == CC * CC)      w_proj = (const float*)d_in[i];
    }
    if (!x || !w_attn || !w_proj) {
        x      = (const float*)d_in[0];
        w_attn = (const float*)d_in[1];
        w_proj = (const float*)d_in[2];
    }
    float* out = (float*)d_out;

    void* p;
    cudaGetSymbolAddress(&p, g_qkv);
    float* qkv = (float*)p;
    cudaGetSymbolAddress(&p, g_xh);
    __nv_bfloat16* xh = (__nv_bfloat16*)p;
    cudaGetSymbolAddress(&p, g_xl);
    __nv_bfloat16* xl = (__nv_bfloat16*)p;
    cudaGetSymbolAddress(&p, g_wah);
    __nv_bfloat16* wah = (__nv_bfloat16*)p;
    cudaGetSymbolAddress(&p, g_wal);
    __nv_bfloat16* wal = (__nv_bfloat16*)p;
    cudaGetSymbolAddress(&p, g_wph);
    __nv_bfloat16* wph = (__nv_bfloat16*)p;
    cudaGetSymbolAddress(&p, g_wpl);
    __nv_bfloat16* wpl = (__nv_bfloat16*)p;
    cudaGetSymbolAddress(&p, g_ath);
    __nv_bfloat16* ath = (__nv_bfloat16*)p;
    cudaGetSymbolAddress(&p, g_atl);
    __nv_bfloat16* atl = (__nv_bfloat16*)p;

    cudaFuncSetAttribute(gemm_tc_kernel,
                         cudaFuncAttributeMaxDynamicSharedMemorySize,
                         GEMM_SMEM_BYTES);
    cudaFuncSetAttribute(attn_kernel,
                         cudaFuncAttributeMaxDynamicSharedMemorySize,
                         ATTN_SMEM_BYTES);

    {
        int n4 = (MROWS * CC) / 4;
        split_kernel<<<(n4 + 255) / 256, 256>>>(x, xh, xl, n4);
    }
    {
        int n4 = (CC * C3) / 4;
        split_kernel<<<(n4 + 255) / 256, 256>>>(w_attn, wah, wal, n4);
    }
    {
        int n4 = (CC * CC) / 4;
        split_kernel<<<(n4 + 255) / 256, 256>>>(w_proj, wph, wpl, n4);
    }
    {
        dim3 grid(C3 / 128, MROWS / 128);
        gemm_tc_kernel<<<grid, 256, GEMM_SMEM_BYTES>>>(xh, xl, wah, wal, qkv, MROWS, C3, CC);
    }
    {
        int total = BB * TT * NH * 32;
        rope_kernel<<<total / 256, 256>>>(qkv);
    }
    {
        int grid = BB * NH * (TT / 64);
        attn_kernel<<<grid, 256, ATTN_SMEM_BYTES>>>(qkv, ath, atl);
    }
    {
        dim3 grid(CC / 128, MROWS / 128);
        gemm_tc_kernel<<<grid, 256, GEMM_SMEM_BYTES>>>(ath, atl, wph, wpl, out, MROWS, CC, CC);
    }
}

// round 14
// speedup vs baseline: 3.2748x; 1.0035x over previous
#include <cuda_runtime.h>
#include <cuda_bf16.h>
#include <cuda_pipeline.h>
#include <mma.h>
#include <math.h>

using namespace nvcuda;

// Problem constants
#define BB 2
#define TT 2048
#define CC 1024
#define NH 16
#define HD 64
#define WINDOW 256
#define SINK 4
#define MROWS (BB*TT)
#define C3 (3*CC)

// Scratch (device globals: no allocation allowed)
__device__ float g_qkv[MROWS * C3];
__device__ __nv_bfloat16 g_qkvh[MROWS * C3];
__device__ __nv_bfloat16 g_qkvl[MROWS * C3];
__device__ __nv_bfloat16 g_xh[MROWS * CC];
__device__ __nv_bfloat16 g_xl[MROWS * CC];
__device__ __nv_bfloat16 g_wah[CC * C3];
__device__ __nv_bfloat16 g_wal[CC * C3];
__device__ __nv_bfloat16 g_wph[CC * CC];
__device__ __nv_bfloat16 g_wpl[CC * CC];
__device__ __nv_bfloat16 g_ath[MROWS * CC];
__device__ __nv_bfloat16 g_atl[MROWS * CC];

__device__ __forceinline__ void split2f(float x, unsigned short& h, unsigned short& l) {
    __nv_bfloat16 hb = __float2bfloat16(x);
    float r = x - __bfloat162float(hb);
    __nv_bfloat16 lb = __float2bfloat16(r);
    h = __bfloat16_as_ushort(hb);
    l = __bfloat16_as_ushort(lb);
}

// ---------------------------------------------------------------------------
// Split fp32 -> bf16 hi + bf16 lo (residual). Vectorized float4 per thread.
// ---------------------------------------------------------------------------
__global__ __launch_bounds__(256)
void split_kernel(const float* __restrict__ src,
                  __nv_bfloat16* __restrict__ dh,
                  __nv_bfloat16* __restrict__ dl, int n4)
{
    int idx = blockIdx.x * blockDim.x + threadIdx.x;
    if (idx >= n4) return;
    float4 v = reinterpret_cast<const float4*>(src)[idx];
    float vals[4];
    vals[0] = v.x;
    vals[1] = v.y;
    vals[2] = v.z;
    vals[3] = v.w;
    unsigned short hs[4];
    unsigned short ls[4];
#pragma unroll
    for (int i = 0; i < 4; i++) {
        split2f(vals[i], hs[i], ls[i]);
    }
    uint2 hp;
    hp.x = (uint32_t)hs[0] | ((uint32_t)hs[1] << 16);
    hp.y = (uint32_t)hs[2] | ((uint32_t)hs[3] << 16);
    uint2 lp;
    lp.x = (uint32_t)ls[0] | ((uint32_t)ls[1] << 16);
    lp.y = (uint32_t)ls[2] | ((uint32_t)ls[3] << 16);
    reinterpret_cast<uint2*>(dh)[idx] = hp;
    reinterpret_cast<uint2*>(dl)[idx] = lp;
}

// ===========================================================================
// Double-buffered split-bf16 GEMM (unchanged from R12/R13 best).
// ===========================================================================
#define GASTRIDE 40
#define GBSTRIDE 136
#define SA_STAGE (128 * GASTRIDE)
#define SB_STAGE (32 * GBSTRIDE)
#define GEMM_SMEM_ELEMS (2 * (2 * SA_STAGE) + 2 * (2 * SB_STAGE))
#define GEMM_SMEM_BYTES (GEMM_SMEM_ELEMS * 2)

__global__ __launch_bounds__(256)
void gemm_tc_kernel(const __nv_bfloat16* __restrict__ Ahg,
                    const __nv_bfloat16* __restrict__ Alg,
                    const __nv_bfloat16* __restrict__ Bhg,
                    const __nv_bfloat16* __restrict__ Blg,
                    float* __restrict__ Cm, int M, int N, int K)
{
    extern __shared__ __nv_bfloat16 dsm[];
    __nv_bfloat16* sAh = dsm;
    __nv_bfloat16* sAl = dsm + 2 * SA_STAGE;
    __nv_bfloat16* sBh = dsm + 4 * SA_STAGE;
    __nv_bfloat16* sBl = dsm + 4 * SA_STAGE + 2 * SB_STAGE;

    const int tid  = threadIdx.x;
    const int warp = tid >> 5;
    const int wm = warp & 3;
    const int wn = warp >> 2;
    const int bm = blockIdx.y * 128;
    const int bn = blockIdx.x * 128;

    wmma::fragment<wmma::accumulator, 16, 16, 16, float> acc[2][4];
#pragma unroll
    for (int mt = 0; mt < 2; mt++) {
#pragma unroll
        for (int nt = 0; nt < 4; nt++) {
            wmma::fill_fragment(acc[mt][nt], 0.0f);
        }
    }

    const int nk = K >> 5;

#pragma unroll
    for (int i = 0; i < 2; i++) {
        int gid = tid + i * 256;
        int arow = gid >> 2;
        int acol = (gid & 3) << 3;
        __pipeline_memcpy_async(&sAh[arow * GASTRIDE + acol],
                                &Ahg[(size_t)(bm + arow) * K + acol], 16);
        __pipeline_memcpy_async(&sAl[arow * GASTRIDE + acol],
                                &Alg[(size_t)(bm + arow) * K + acol], 16);
        int brow = gid >> 4;
        int bcol = (gid & 15) << 3;
        __pipeline_memcpy_async(&sBh[brow * GBSTRIDE + bcol],
                                &Bhg[(size_t)brow * N + bn + bcol], 16);
        __pipeline_memcpy_async(&sBl[brow * GBSTRIDE + bcol],
                                &Blg[(size_t)brow * N + bn + bcol], 16);
    }
    __pipeline_commit();

    for (int ks = 0; ks < nk; ks++) {
        __pipeline_wait_prior(0);
        __syncthreads();

        if (ks + 1 < nk) {
            const int k0 = (ks + 1) << 5;
            const int st = (ks + 1) & 1;
            const int ao = st * SA_STAGE;
            const int bo = st * SB_STAGE;
#pragma unroll
            for (int i = 0; i < 2; i++) {
                int gid = tid + i * 256;
                int arow = gid >> 2;
                int acol = (gid & 3) << 3;
                __pipeline_memcpy_async(&sAh[ao + arow * GASTRIDE + acol],
                                        &Ahg[(size_t)(bm + arow) * K + k0 + acol], 16);
                __pipeline_memcpy_async(&sAl[ao + arow * GASTRIDE + acol],
                                        &Alg[(size_t)(bm + arow) * K + k0 + acol], 16);
                int brow = gid >> 4;
                int bcol = (gid & 15) << 3;
                __pipeline_memcpy_async(&sBh[bo + brow * GBSTRIDE + bcol],
                                        &Bhg[(size_t)(k0 + brow) * N + bn + bcol], 16);
                __pipeline_memcpy_async(&sBl[bo + brow * GBSTRIDE + bcol],
                                        &Blg[(size_t)(k0 + brow) * N + bn + bcol], 16);
            }
            __pipeline_commit();
        }

        const int cur = ks & 1;
        const int ao = cur * SA_STAGE;
        const int bo = cur * SB_STAGE;

#pragma unroll
        for (int k16 = 0; k16 < 2; k16++) {
            const int kk = k16 << 4;
            wmma::fragment<wmma::matrix_a, 16, 16, 16, __nv_bfloat16, wmma::row_major> fa_h[2];
            wmma::fragment<wmma::matrix_a, 16, 16, 16, __nv_bfloat16, wmma::row_major> fa_l[2];
            wmma::fragment<wmma::matrix_b, 16, 16, 16, __nv_bfloat16, wmma::row_major> fb_h[4];
            wmma::fragment<wmma::matrix_b, 16, 16, 16, __nv_bfloat16, wmma::row_major> fb_l[4];
#pragma unroll
            for (int mt = 0; mt < 2; mt++) {
                const __nv_bfloat16* pa = &sAh[ao + (wm * 32 + mt * 16) * GASTRIDE + kk];
                wmma::load_matrix_sync(fa_h[mt], pa, GASTRIDE);
                const __nv_bfloat16* pl = &sAl[ao + (wm * 32 + mt * 16) * GASTRIDE + kk];
                wmma::load_matrix_sync(fa_l[mt], pl, GASTRIDE);
            }
#pragma unroll
            for (int nt = 0; nt < 4; nt++) {
                const __nv_bfloat16* pb = &sBh[bo + kk * GBSTRIDE + wn * 64 + nt * 16];
                wmma::load_matrix_sync(fb_h[nt], pb, GBSTRIDE);
                const __nv_bfloat16* pl = &sBl[bo + kk * GBSTRIDE + wn * 64 + nt * 16];
                wmma::load_matrix_sync(fb_l[nt], pl, GBSTRIDE);
            }
#pragma unroll
            for (int mt = 0; mt < 2; mt++) {
#pragma unroll
                for (int nt = 0; nt < 4; nt++) {
                    wmma::mma_sync(acc[mt][nt], fa_h[mt], fb_h[nt], acc[mt][nt]);
                    wmma::mma_sync(acc[mt][nt], fa_h[mt], fb_l[nt], acc[mt][nt]);
                    wmma::mma_sync(acc[mt][nt], fa_l[mt], fb_h[nt], acc[mt][nt]);
                }
            }
        }
    }

#pragma unroll
    for (int mt = 0; mt < 2; mt++) {
        int row0 = bm + wm * 32 + mt * 16;
#pragma unroll
        for (int nt = 0; nt < 4; nt++) {
            int col0 = bn + wn * 64 + nt * 16;
            float* dst = &Cm[(size_t)row0 * N + col0];
            wmma::store_matrix_sync(dst, acc[mt][nt], N, wmma::mem_row_major);
        }
    }
}

// ---------------------------------------------------------------------------
// RoPE + split: reads fp32 qkv, applies RoPE to q (folding exact 0.125 scale)
// and k, passes v through; writes bf16 hi/lo arrays (same [row, 3C] layout).
// One thread per (b,t,h,d2), d2 in [0,32).
// ---------------------------------------------------------------------------
__global__ __launch_bounds__(256)
void rope_split_kernel(const float* __restrict__ qkv,
                       __nv_bfloat16* __restrict__ oh,
                       __nv_bfloat16* __restrict__ ol)
{
    int idx = blockIdx.x * blockDim.x + threadIdx.x;
    int d2 = idx & 31;
    int h  = (idx >> 5) & (NH - 1);
    int t  = (idx >> 9) & (TT - 1);
    int b  = idx >> 20;
    if (b >= BB) return;

    float invf = 1.0f / powf(10000.0f, (float)d2 / 32.0f);
    float ang  = (float)t * invf;
    float c = (float)cos((double)ang);
    float s = (float)sin((double)ang);

    size_t base = (size_t)(b * TT + t) * C3 + h * HD;
    unsigned short hh;
    unsigned short ll;

    // q: rope + exact 0.125 scale
    {
        float a0 = qkv[base + d2];
        float a1 = qkv[base + d2 + 32];
        float r0 = (a0 * c - a1 * s) * 0.125f;
        float r1 = (a1 * c + a0 * s) * 0.125f;
        split2f(r0, hh, ll);
        oh[base + d2] = __ushort_as_bfloat16(hh);
        ol[base + d2] = __ushort_as_bfloat16(ll);
        split2f(r1, hh, ll);
        oh[base + d2 + 32] = __ushort_as_bfloat16(hh);
        ol[base + d2 + 32] = __ushort_as_bfloat16(ll);
    }
    // k: rope only
    {
        float a0 = qkv[base + CC + d2];
        float a1 = qkv[base + CC + d2 + 32];
        float r0 = a0 * c - a1 * s;
        float r1 = a1 * c + a0 * s;
        split2f(r0, hh, ll);
        oh[base + CC + d2] = __ushort_as_bfloat16(hh);
        ol[base + CC + d2] = __ushort_as_bfloat16(ll);
        split2f(r1, hh, ll);
        oh[base + CC + d2 + 32] = __ushort_as_bfloat16(hh);
        ol[base + CC + d2 + 32] = __ushort_as_bfloat16(ll);
    }
    // v: pass-through split
    {
        float a0 = qkv[base + 2 * CC + d2];
        float a1 = qkv[base + 2 * CC + d2 + 32];
        split2f(a0, hh, ll);
        oh[base + 2 * CC + d2] = __ushort_as_bfloat16(hh);
        ol[base + 2 * CC + d2] = __ushort_as_bfloat16(ll);
        split2f(a1, hh, ll);
        oh[base + 2 * CC + d2 + 32] = __ushort_as_bfloat16(hh);
        ol[base + 2 * CC + d2 + 32] = __ushort_as_bfloat16(ll);
    }
}

// ---------------------------------------------------------------------------
// Tensor-core windowed attention; inputs pre-split bf16 hi/lo (no conversion
// in-kernel). Structure identical to R13.
// ---------------------------------------------------------------------------
#define CHUNK 32
#define AQ_STR 72
#define AS_STR 36
#define AP_STR 40
#define AO_STR 72

#define OFF_QH 0
#define OFF_QL 9216
#define OFF_KH 18432
#define OFF_KL 23040
#define OFF_VH 27648
#define OFF_VL 32256
#define OFF_S  36864
#define OFF_PH 46080
#define OFF_PL 51200
#define OFF_O  56320
#define ATTN_SMEM_BYTES 74752

__global__ __launch_bounds__(256)
void attn_kernel(const __nv_bfloat16* __restrict__ qh,
                 const __nv_bfloat16* __restrict__ ql,
                 __nv_bfloat16* __restrict__ ath,
                 __nv_bfloat16* __restrict__ atl)
{
    extern __shared__ char smraw[];
    __nv_bfloat16* Qh = reinterpret_cast<__nv_bfloat16*>(smraw + OFF_QH);
    __nv_bfloat16* Ql = reinterpret_cast<__nv_bfloat16*>(smraw + OFF_QL);
    __nv_bfloat16* Kh = reinterpret_cast<__nv_bfloat16*>(smraw + OFF_KH);
    __nv_bfloat16* Kl = reinterpret_cast<__nv_bfloat16*>(smraw + OFF_KL);
    __nv_bfloat16* Vh = reinterpret_cast<__nv_bfloat16*>(smraw + OFF_VH);
    __nv_bfloat16* Vl = reinterpret_cast<__nv_bfloat16*>(smraw + OFF_VL);
    float* Ssm = reinterpret_cast<float*>(smraw + OFF_S);
    __nv_bfloat16* Ph = reinterpret_cast<__nv_bfloat16*>(smraw + OFF_PH);
    __nv_bfloat16* Pl = reinterpret_cast<__nv_bfloat16*>(smraw + OFF_PL);
    float* Osm = reinterpret_cast<float*>(smraw + OFF_O);

    const int tid = threadIdx.x;
    const int warp = tid >> 5;
    const int bid = blockIdx.x;
    const int qb = bid & 31;
    const int h  = (bid >> 5) & (NH - 1);
    const int b  = bid >> 9;
    const int q0 = qb * 64;
    const int sq = tid >> 3;
    const int kt = tid & 7;

    // Q tile: 64x64 bf16 hi/lo, direct 16B copies (scale already folded)
#pragma unroll
    for (int i = 0; i < 2; i++) {
        int f = tid + i * 256;
        int r = f >> 3;
        int seg = (f & 7) << 3;
        size_t gb = (size_t)(b * TT + q0 + r) * C3 + h * HD + seg;
        *reinterpret_cast<uint4*>(&Qh[r * AQ_STR + seg]) =
            *reinterpret_cast<const uint4*>(&qh[gb]);
        *reinterpret_cast<uint4*>(&Ql[r * AQ_STR + seg]) =
            *reinterpret_cast<const uint4*>(&ql[gb]);
    }
#pragma unroll
    for (int i = 0; i < 18; i++) {
        Osm[tid + i * 256] = 0.f;
    }

    float m1 = -1e30f;
    float l1 = 0.f;
    float m2 = -1e30f;
    float l2 = 0.f;

    const int cstart = (q0 - WINDOW > 0) ? (q0 - WINDOW) : 0;
    const int do_sink = (cstart > 0) ? 1 : 0;
    const int nwin = (q0 + 64 - cstart) / CHUNK;
    const int nch = nwin + do_sink;

    for (int phase = 0; phase < nch; phase++) {
        const int c = (do_sink && phase == 0) ? 0 : cstart + (phase - do_sink) * CHUNK;

        __syncthreads();
        // K/V chunk: 32x64 bf16 hi/lo, one 16B copy per array per thread
        {
            int r = tid >> 3;
            int seg = (tid & 7) << 3;
            size_t gb = (size_t)(b * TT + c + r) * C3 + h * HD + seg;
            *reinterpret_cast<uint4*>(&Kh[r * AQ_STR + seg]) =
                *reinterpret_cast<const uint4*>(&qh[gb + CC]);
            *reinterpret_cast<uint4*>(&Kl[r * AQ_STR + seg]) =
                *reinterpret_cast<const uint4*>(&ql[gb + CC]);
            *reinterpret_cast<uint4*>(&Vh[r * AQ_STR + seg]) =
                *reinterpret_cast<const uint4*>(&qh[gb + 2 * CC]);
            *reinterpret_cast<uint4*>(&Vl[r * AQ_STR + seg]) =
                *reinterpret_cast<const uint4*>(&ql[gb + 2 * CC]);
        }
        __syncthreads();

        // ---- scores via wmma ----
        {
            const int qr = (warp & 3) * 16;
            const int kc = (warp >> 2) * 16;
            wmma::fragment<wmma::accumulator, 16, 16, 16, float> acc_s;
            wmma::fill_fragment(acc_s, 0.0f);
#pragma unroll
            for (int d4 = 0; d4 < 4; d4++) {
                wmma::fragment<wmma::matrix_a, 16, 16, 16, __nv_bfloat16, wmma::row_major> fa_h;
                wmma::fragment<wmma::matrix_a, 16, 16, 16, __nv_bfloat16, wmma::row_major> fa_l;
                wmma::fragment<wmma::matrix_b, 16, 16, 16, __nv_bfloat16, wmma::col_major> fb_h;
                wmma::fragment<wmma::matrix_b, 16, 16, 16, __nv_bfloat16, wmma::col_major> fb_l;
                wmma::load_matrix_sync(fa_h, &Qh[qr * AQ_STR + d4 * 16], AQ_STR);
                wmma::load_matrix_sync(fa_l, &Ql[qr * AQ_STR + d4 * 16], AQ_STR);
                wmma::load_matrix_sync(fb_h, &Kh[kc * AQ_STR + d4 * 16], AQ_STR);
                wmma::load_matrix_sync(fb_l, &Kl[kc * AQ_STR + d4 * 16], AQ_STR);
                wmma::mma_sync(acc_s, fa_h, fb_h, acc_s);
                wmma::mma_sync(acc_s, fa_h, fb_l, acc_s);
                wmma::mma_sync(acc_s, fa_l, fb_h, acc_s);
            }
            wmma::store_matrix_sync(&Ssm[qr * AS_STR + kc], acc_s, AS_STR, wmma::mem_row_major);
        }
        __syncthreads();

        // ---- scalar online softmax ----
        {
            float s1[4];
            float s2[4];
#pragma unroll
            for (int kki = 0; kki < 4; kki++) {
                s1[kki] = Ssm[sq * AS_STR + kt + kki * 8];
                s2[kki] = Ssm[(sq + 32) * AS_STR + kt + kki * 8];
            }
            const int qq1 = q0 + sq;
            const int qq2 = q0 + sq + 32;
            float mc1 = -1e30f;
            float mc2 = -1e30f;
#pragma unroll
            for (int kki = 0; kki < 4; kki++) {
                int j = c + kt + kki * 8;
                bool a1 = (j <= qq1) && (((qq1 - j) < WINDOW) || (j < SINK));
                if (!a1) s1[kki] = -1e30f;
                mc1 = fmaxf(mc1, s1[kki]);
                bool a2 = (j <= qq2) && (((qq2 - j) < WINDOW) || (j < SINK));
                if (!a2) s2[kki] = -1e30f;
                mc2 = fmaxf(mc2, s2[kki]);
            }
            mc1 = fmaxf(mc1, __shfl_xor_sync(0xffffffffu, mc1, 1));
            mc1 = fmaxf(mc1, __shfl_xor_sync(0xffffffffu, mc1, 2));
            mc1 = fmaxf(mc1, __shfl_xor_sync(0xffffffffu, mc1, 4));
            mc2 = fmaxf(mc2, __shfl_xor_sync(0xffffffffu, mc2, 1));
            mc2 = fmaxf(mc2, __shfl_xor_sync(0xffffffffu, mc2, 2));
            mc2 = fmaxf(mc2, __shfl_xor_sync(0xffffffffu, mc2, 4));
            float mn1 = fmaxf(m1, mc1);
            float mn2 = fmaxf(m2, mc2);
            float alpha1 = expf(m1 - mn1);
            float alpha2 = expf(m2 - mn2);

            float lc1 = 0.f;
            float lc2 = 0.f;
#pragma unroll
            for (int kki = 0; kki < 4; kki++) {
                int j = kt + kki * 8;
                float p1 = expf(s1[kki] - mn1);
                lc1 += p1;
                unsigned short hh;
                unsigned short ll;
                split2f(p1, hh, ll);
                Ph[sq * AP_STR + j] = __ushort_as_bfloat16(hh);
                Pl[sq * AP_STR + j] = __ushort_as_bfloat16(ll);
                float p2 = expf(s2[kki] - mn2);
                lc2 += p2;
                split2f(p2, hh, ll);
                Ph[(sq + 32) * AP_STR + j] = __ushort_as_bfloat16(hh);
                Pl[(sq + 32) * AP_STR + j] = __ushort_as_bfloat16(ll);
            }
            lc1 += __shfl_xor_sync(0xffffffffu, lc1, 1);
            lc1 += __shfl_xor_sync(0xffffffffu, lc1, 2);
            lc1 += __shfl_xor_sync(0xffffffffu, lc1, 4);
            lc2 += __shfl_xor_sync(0xffffffffu, lc2, 1);
            lc2 += __shfl_xor_sync(0xffffffffu, lc2, 2);
            lc2 += __shfl_xor_sync(0xffffffffu, lc2, 4);
            l1 = l1 * alpha1 + lc1;
            l2 = l2 * alpha2 + lc2;
            m1 = mn1;
            m2 = mn2;

#pragma unroll
            for (int e = 0; e < 4; e++) {
                Osm[sq * AO_STR + kt * 4 + e] *= alpha1;
                Osm[sq * AO_STR + kt * 4 + 32 + e] *= alpha1;
                Osm[(sq + 32) * AO_STR + kt * 4 + e] *= alpha2;
                Osm[(sq + 32) * AO_STR + kt * 4 + 32 + e] *= alpha2;
            }
        }
        __syncthreads();

        // ---- PV via wmma ----
        {
            const int qr = (warp & 3) * 16;
            const int vc0 = (warp >> 2) * 32;
            wmma::fragment<wmma::matrix_a, 16, 16, 16, __nv_bfloat16, wmma::row_major> pa_h[2];
            wmma::fragment<wmma::matrix_a, 16, 16, 16, __nv_bfloat16, wmma::row_major> pa_l[2];
#pragma unroll
            for (int k16 = 0; k16 < 2; k16++) {
                wmma::load_matrix_sync(pa_h[k16], &Ph[qr * AP_STR + k16 * 16], AP_STR);
                wmma::load_matrix_sync(pa_l[k16], &Pl[qr * AP_STR + k16 * 16], AP_STR);
            }
#pragma unroll
            for (int cf = 0; cf < 2; cf++) {
                const int vc = vc0 + cf * 16;
                wmma::fragment<wmma::accumulator, 16, 16, 16, float> acc_o;
                wmma::load_matrix_sync(acc_o, &Osm[qr * AO_STR + vc], AO_STR, wmma::mem_row_major);
#pragma unroll
                for (int k16 = 0; k16 < 2; k16++) {
                    wmma::fragment<wmma::matrix_b, 16, 16, 16, __nv_bfloat16, wmma::row_major> vb_h;
                    wmma::fragment<wmma::matrix_b, 16, 16, 16, __nv_bfloat16, wmma::row_major> vb_l;
                    wmma::load_matrix_sync(vb_h, &Vh[(k16 * 16) * AQ_STR + vc], AQ_STR);
                    wmma::load_matrix_sync(vb_l, &Vl[(k16 * 16) * AQ_STR + vc], AQ_STR);
                    wmma::mma_sync(acc_o, pa_h[k16], vb_h, acc_o);
                    wmma::mma_sync(acc_o, pa_h[k16], vb_l, acc_o);
                    wmma::mma_sync(acc_o, pa_l[k16], vb_h, acc_o);
                }
                wmma::store_matrix_sync(&Osm[qr * AO_STR + vc], acc_o, AO_STR, wmma::mem_row_major);
            }
        }
    }

    __syncthreads();

    float inv1 = 1.0f / l1;
    float inv2 = 1.0f / l2;
#pragma unroll
    for (int qi = 0; qi < 2; qi++) {
        float inv = (qi == 0) ? inv1 : inv2;
        int row = sq + qi * 32;
        size_t rowbase = (size_t)(b * TT + q0 + row) * CC + h * HD;
#pragma unroll
        for (int half = 0; half < 2; half++) {
            unsigned short hs[4];
            unsigned short ls[4];
#pragma unroll
            for (int e = 0; e < 4; e++) {
                float val = Osm[row * AO_STR + kt * 4 + half * 32 + e] * inv;
                split2f(val, hs[e], ls[e]);
            }
            uint2 hp;
            hp.x = (uint32_t)hs[0] | ((uint32_t)hs[1] << 16);
            hp.y = (uint32_t)hs[2] | ((uint32_t)hs[3] << 16);
            uint2 lp;
            lp.x = (uint32_t)ls[0] | ((uint32_t)ls[1] << 16);
            lp.y = (uint32_t)ls[2] | ((uint32_t)ls[3] << 16);
            size_t off = rowbase + kt * 4 + half * 32;
            *reinterpret_cast<uint2*>(&ath[off]) = hp;
            *reinterpret_cast<uint2*>(&atl[off]) = lp;
        }
    }
}

// ---------------------------------------------------------------------------
extern "C" void kernel_launch(void* const* d_in, const int* in_sizes, int n_in,
                              void* d_out, int out_size)
{
    const float* x = nullptr;
    const float* w_attn = nullptr;
    const float* w_proj = nullptr;
    for (int i = 0; i < n_in; i++) {
        if (in_sizes[i] == BB * TT * CC)      x      = (const float*)d_in[i];
        else if (in_sizes[i] == CC * C3)      w_attn = (const float*)d_in[i];
        else if (in_sizes[i] == CC * CC)      w_proj = (const float*)d_in[i];
    }
    if (!x || !w_attn || !w_proj) {
        x      = (const float*)d_in[0];
        w_attn = (const float*)d_in[1];
        w_proj = (const float*)d_in[2];
    }
    float* out = (float*)d_out;

    void* p;
    cudaGetSymbolAddress(&p, g_qkv);
    float* qkv = (float*)p;
    cudaGetSymbolAddress(&p, g_qkvh);
    __nv_bfloat16* qkvh = (__nv_bfloat16*)p;
    cudaGetSymbolAddress(&p, g_qkvl);
    __nv_bfloat16* qkvl = (__nv_bfloat16*)p;
    cudaGetSymbolAddress(&p, g_xh);
    __nv_bfloat16* xh = (__nv_bfloat16*)p;
    cudaGetSymbolAddress(&p, g_xl);
    __nv_bfloat16* xl = (__nv_bfloat16*)p;
    cudaGetSymbolAddress(&p, g_wah);
    __nv_bfloat16* wah = (__nv_bfloat16*)p;
    cudaGetSymbolAddress(&p, g_wal);
    __nv_bfloat16* wal = (__nv_bfloat16*)p;
    cudaGetSymbolAddress(&p, g_wph);
    __nv_bfloat16* wph = (__nv_bfloat16*)p;
    cudaGetSymbolAddress(&p, g_wpl);
    __nv_bfloat16* wpl = (__nv_bfloat16*)p;
    cudaGetSymbolAddress(&p, g_ath);
    __nv_bfloat16* ath = (__nv_bfloat16*)p;
    cudaGetSymbolAddress(&p, g_atl);
    __nv_bfloat16* atl = (__nv_bfloat16*)p;

    cudaFuncSetAttribute(gemm_tc_kernel,
                         cudaFuncAttributeMaxDynamicSharedMemorySize,
                         GEMM_SMEM_BYTES);
    cudaFuncSetAttribute(attn_kernel,
                         cudaFuncAttributeMaxDynamicSharedMemorySize,
                         ATTN_SMEM_BYTES);

    {
        int n4 = (MROWS * CC) / 4;
        split_kernel<<<(n4 + 255) / 256, 256>>>(x, xh, xl, n4);
    }
    {
        int n4 = (CC * C3) / 4;
        split_kernel<<<(n4 + 255) / 256, 256>>>(w_attn, wah, wal, n4);
    }
    {
        int n4 = (CC * CC) / 4;
        split_kernel<<<(n4 + 255) / 256, 256>>>(w_proj, wph, wpl, n4);
    }
    {
        dim3 grid(C3 / 128, MROWS / 128);
        gemm_tc_kernel<<<grid, 256, GEMM_SMEM_BYTES>>>(xh, xl, wah, wal, qkv, MROWS, C3, CC);
    }
    {
        int total = BB * TT * NH * 32;
        rope_split_kernel<<<total / 256, 256>>>(qkv, qkvh, qkvl);
    }
    {
        int grid = BB * NH * (TT / 64);
        attn_kernel<<<grid, 256, ATTN_SMEM_BYTES>>>(qkvh, qkvl, ath, atl);
    }
    {
        dim3 grid(CC / 128, MROWS / 128);
        gemm_tc_kernel<<<grid, 256, GEMM_SMEM_BYTES>>>(ath, atl, wph, wpl, out, MROWS, CC, CC);
    }
}

// round 17
// speedup vs baseline: 3.3690x; 1.0288x over previous
#include <cuda_runtime.h>
#include <cuda_bf16.h>
#include <cuda_pipeline.h>
#include <mma.h>
#include <math.h>

using namespace nvcuda;

// Problem constants
#define BB 2
#define TT 2048
#define CC 1024
#define NH 16
#define HD 64
#define WINDOW 256
#define SINK 4
#define MROWS (BB*TT)
#define C3 (3*CC)

// Scratch (device globals: no allocation allowed)
__device__ float g_qkv[MROWS * C3];
__device__ __nv_bfloat16 g_qkvh[MROWS * C3];
__device__ __nv_bfloat16 g_qkvl[MROWS * C3];
__device__ __nv_bfloat16 g_xh[MROWS * CC];
__device__ __nv_bfloat16 g_xl[MROWS * CC];
__device__ __nv_bfloat16 g_wah[CC * C3];
__device__ __nv_bfloat16 g_wal[CC * C3];
__device__ __nv_bfloat16 g_wph[CC * CC];
__device__ __nv_bfloat16 g_wpl[CC * CC];
__device__ __nv_bfloat16 g_ath[MROWS * CC];
__device__ __nv_bfloat16 g_atl[MROWS * CC];

__device__ __forceinline__ void split2f(float x, unsigned short& h, unsigned short& l) {
    __nv_bfloat16 hb = __float2bfloat16(x);
    float r = x - __bfloat162float(hb);
    __nv_bfloat16 lb = __float2bfloat16(r);
    h = __bfloat16_as_ushort(hb);
    l = __bfloat16_as_ushort(lb);
}

// ---------------------------------------------------------------------------
// Split fp32 -> bf16 hi + bf16 lo (residual). Vectorized float4 per thread.
// ---------------------------------------------------------------------------
__global__ __launch_bounds__(256)
void split_kernel(const float* __restrict__ src,
                  __nv_bfloat16* __restrict__ dh,
                  __nv_bfloat16* __restrict__ dl, int n4)
{
    int idx = blockIdx.x * blockDim.x + threadIdx.x;
    if (idx >= n4) return;
    float4 v = reinterpret_cast<const float4*>(src)[idx];
    float vals[4];
    vals[0] = v.x;
    vals[1] = v.y;
    vals[2] = v.z;
    vals[3] = v.w;
    unsigned short hs[4];
    unsigned short ls[4];
#pragma unroll
    for (int i = 0; i < 4; i++) {
        split2f(vals[i], hs[i], ls[i]);
    }
    uint2 hp;
    hp.x = (uint32_t)hs[0] | ((uint32_t)hs[1] << 16);
    hp.y = (uint32_t)hs[2] | ((uint32_t)hs[3] << 16);
    uint2 lp;
    lp.x = (uint32_t)ls[0] | ((uint32_t)ls[1] << 16);
    lp.y = (uint32_t)ls[2] | ((uint32_t)ls[3] << 16);
    reinterpret_cast<uint2*>(dh)[idx] = hp;
    reinterpret_cast<uint2*>(dl)[idx] = lp;
}

// ===========================================================================
// Double-buffered split-bf16 GEMM (unchanged from R12-R14 best).
// ===========================================================================
#define GASTRIDE 40
#define GBSTRIDE 136
#define SA_STAGE (128 * GASTRIDE)
#define SB_STAGE (32 * GBSTRIDE)
#define GEMM_SMEM_ELEMS (2 * (2 * SA_STAGE) + 2 * (2 * SB_STAGE))
#define GEMM_SMEM_BYTES (GEMM_SMEM_ELEMS * 2)

__global__ __launch_bounds__(256)
void gemm_tc_kernel(const __nv_bfloat16* __restrict__ Ahg,
                    const __nv_bfloat16* __restrict__ Alg,
                    const __nv_bfloat16* __restrict__ Bhg,
                    const __nv_bfloat16* __restrict__ Blg,
                    float* __restrict__ Cm, int M, int N, int K)
{
    extern __shared__ __nv_bfloat16 dsm[];
    __nv_bfloat16* sAh = dsm;
    __nv_bfloat16* sAl = dsm + 2 * SA_STAGE;
    __nv_bfloat16* sBh = dsm + 4 * SA_STAGE;
    __nv_bfloat16* sBl = dsm + 4 * SA_STAGE + 2 * SB_STAGE;

    const int tid  = threadIdx.x;
    const int warp = tid >> 5;
    const int wm = warp & 3;
    const int wn = warp >> 2;
    const int bm = blockIdx.y * 128;
    const int bn = blockIdx.x * 128;

    wmma::fragment<wmma::accumulator, 16, 16, 16, float> acc[2][4];
#pragma unroll
    for (int mt = 0; mt < 2; mt++) {
#pragma unroll
        for (int nt = 0; nt < 4; nt++) {
            wmma::fill_fragment(acc[mt][nt], 0.0f);
        }
    }

    const int nk = K >> 5;

#pragma unroll
    for (int i = 0; i < 2; i++) {
        int gid = tid + i * 256;
        int arow = gid >> 2;
        int acol = (gid & 3) << 3;
        __pipeline_memcpy_async(&sAh[arow * GASTRIDE + acol],
                                &Ahg[(size_t)(bm + arow) * K + acol], 16);
        __pipeline_memcpy_async(&sAl[arow * GASTRIDE + acol],
                                &Alg[(size_t)(bm + arow) * K + acol], 16);
        int brow = gid >> 4;
        int bcol = (gid & 15) << 3;
        __pipeline_memcpy_async(&sBh[brow * GBSTRIDE + bcol],
                                &Bhg[(size_t)brow * N + bn + bcol], 16);
        __pipeline_memcpy_async(&sBl[brow * GBSTRIDE + bcol],
                                &Blg[(size_t)brow * N + bn + bcol], 16);
    }
    __pipeline_commit();

    for (int ks = 0; ks < nk; ks++) {
        __pipeline_wait_prior(0);
        __syncthreads();

        if (ks + 1 < nk) {
            const int k0 = (ks + 1) << 5;
            const int st = (ks + 1) & 1;
            const int ao = st * SA_STAGE;
            const int bo = st * SB_STAGE;
#pragma unroll
            for (int i = 0; i < 2; i++) {
                int gid = tid + i * 256;
                int arow = gid >> 2;
                int acol = (gid & 3) << 3;
                __pipeline_memcpy_async(&sAh[ao + arow * GASTRIDE + acol],
                                        &Ahg[(size_t)(bm + arow) * K + k0 + acol], 16);
                __pipeline_memcpy_async(&sAl[ao + arow * GASTRIDE + acol],
                                        &Alg[(size_t)(bm + arow) * K + k0 + acol], 16);
                int brow = gid >> 4;
                int bcol = (gid & 15) << 3;
                __pipeline_memcpy_async(&sBh[bo + brow * GBSTRIDE + bcol],
                                        &Bhg[(size_t)(k0 + brow) * N + bn + bcol], 16);
                __pipeline_memcpy_async(&sBl[bo + brow * GBSTRIDE + bcol],
                                        &Blg[(size_t)(k0 + brow) * N + bn + bcol], 16);
            }
            __pipeline_commit();
        }

        const int cur = ks & 1;
        const int ao = cur * SA_STAGE;
        const int bo = cur * SB_STAGE;

#pragma unroll
        for (int k16 = 0; k16 < 2; k16++) {
            const int kk = k16 << 4;
            wmma::fragment<wmma::matrix_a, 16, 16, 16, __nv_bfloat16, wmma::row_major> fa_h[2];
            wmma::fragment<wmma::matrix_a, 16, 16, 16, __nv_bfloat16, wmma::row_major> fa_l[2];
            wmma::fragment<wmma::matrix_b, 16, 16, 16, __nv_bfloat16, wmma::row_major> fb_h[4];
            wmma::fragment<wmma::matrix_b, 16, 16, 16, __nv_bfloat16, wmma::row_major> fb_l[4];
#pragma unroll
            for (int mt = 0; mt < 2; mt++) {
                const __nv_bfloat16* pa = &sAh[ao + (wm * 32 + mt * 16) * GASTRIDE + kk];
                wmma::load_matrix_sync(fa_h[mt], pa, GASTRIDE);
                const __nv_bfloat16* pl = &sAl[ao + (wm * 32 + mt * 16) * GASTRIDE + kk];
                wmma::load_matrix_sync(fa_l[mt], pl, GASTRIDE);
            }
#pragma unroll
            for (int nt = 0; nt < 4; nt++) {
                const __nv_bfloat16* pb = &sBh[bo + kk * GBSTRIDE + wn * 64 + nt * 16];
                wmma::load_matrix_sync(fb_h[nt], pb, GBSTRIDE);
                const __nv_bfloat16* pl = &sBl[bo + kk * GBSTRIDE + wn * 64 + nt * 16];
                wmma::load_matrix_sync(fb_l[nt], pl, GBSTRIDE);
            }
#pragma unroll
            for (int mt = 0; mt < 2; mt++) {
#pragma unroll
                for (int nt = 0; nt < 4; nt++) {
                    wmma::mma_sync(acc[mt][nt], fa_h[mt], fb_h[nt], acc[mt][nt]);
                    wmma::mma_sync(acc[mt][nt], fa_h[mt], fb_l[nt], acc[mt][nt]);
                    wmma::mma_sync(acc[mt][nt], fa_l[mt], fb_h[nt], acc[mt][nt]);
                }
            }
        }
    }

#pragma unroll
    for (int mt = 0; mt < 2; mt++) {
        int row0 = bm + wm * 32 + mt * 16;
#pragma unroll
        for (int nt = 0; nt < 4; nt++) {
            int col0 = bn + wn * 64 + nt * 16;
            float* dst = &Cm[(size_t)row0 * N + col0];
            wmma::store_matrix_sync(dst, acc[mt][nt], N, wmma::mem_row_major);
        }
    }
}

// ---------------------------------------------------------------------------
// RoPE + split: reads fp32 qkv, applies RoPE to q (folding exact 0.125 scale)
// and k, passes v through; writes bf16 hi/lo arrays.
// ---------------------------------------------------------------------------
__global__ __launch_bounds__(256)
void rope_split_kernel(const float* __restrict__ qkv,
                       __nv_bfloat16* __restrict__ oh,
                       __nv_bfloat16* __restrict__ ol)
{
    int idx = blockIdx.x * blockDim.x + threadIdx.x;
    int d2 = idx & 31;
    int h  = (idx >> 5) & (NH - 1);
    int t  = (idx >> 9) & (TT - 1);
    int b  = idx >> 20;
    if (b >= BB) return;

    float invf = 1.0f / powf(10000.0f, (float)d2 / 32.0f);
    float ang  = (float)t * invf;
    float c = (float)cos((double)ang);
    float s = (float)sin((double)ang);

    size_t base = (size_t)(b * TT + t) * C3 + h * HD;
    unsigned short hh;
    unsigned short ll;

    {
        float a0 = qkv[base + d2];
        float a1 = qkv[base + d2 + 32];
        float r0 = (a0 * c - a1 * s) * 0.125f;
        float r1 = (a1 * c + a0 * s) * 0.125f;
        split2f(r0, hh, ll);
        oh[base + d2] = __ushort_as_bfloat16(hh);
        ol[base + d2] = __ushort_as_bfloat16(ll);
        split2f(r1, hh, ll);
        oh[base + d2 + 32] = __ushort_as_bfloat16(hh);
        ol[base + d2 + 32] = __ushort_as_bfloat16(ll);
    }
    {
        float a0 = qkv[base + CC + d2];
        float a1 = qkv[base + CC + d2 + 32];
        float r0 = a0 * c - a1 * s;
        float r1 = a1 * c + a0 * s;
        split2f(r0, hh, ll);
        oh[base + CC + d2] = __ushort_as_bfloat16(hh);
        ol[base + CC + d2] = __ushort_as_bfloat16(ll);
        split2f(r1, hh, ll);
        oh[base + CC + d2 + 32] = __ushort_as_bfloat16(hh);
        ol[base + CC + d2 + 32] = __ushort_as_bfloat16(ll);
    }
    {
        float a0 = qkv[base + 2 * CC + d2];
        float a1 = qkv[base + 2 * CC + d2 + 32];
        split2f(a0, hh, ll);
        oh[base + 2 * CC + d2] = __ushort_as_bfloat16(hh);
        ol[base + 2 * CC + d2] = __ushort_as_bfloat16(ll);
        split2f(a1, hh, ll);
        oh[base + 2 * CC + d2 + 32] = __ushort_as_bfloat16(hh);
        ol[base + 2 * CC + d2 + 32] = __ushort_as_bfloat16(ll);
    }
}

// ---------------------------------------------------------------------------
// Tensor-core windowed attention, CHUNK=64 (halves the phase/barrier count).
// Per 64-key chunk: S[64x64] via wmma (2 frags/warp, A-frags hoisted),
// scalar online softmax (8 keys/lane), PV via wmma (P-frags hoisted).
// ---------------------------------------------------------------------------
#define CHUNK 64
#define AQ_STR 72
#define AS_STR 68
#define AP_STR 72
#define AO_STR 72

#define OFF_QH 0
#define OFF_QL 9216
#define OFF_KH 18432
#define OFF_KL 27648
#define OFF_VH 36864
#define OFF_VL 46080
#define OFF_S  55296
#define OFF_PH 72704
#define OFF_PL 81920
#define OFF_O  91136
#define ATTN_SMEM_BYTES 109568

__global__ __launch_bounds__(256)
void attn_kernel(const __nv_bfloat16* __restrict__ qh,
                 const __nv_bfloat16* __restrict__ ql,
                 __nv_bfloat16* __restrict__ ath,
                 __nv_bfloat16* __restrict__ atl)
{
    extern __shared__ char smraw[];
    __nv_bfloat16* Qh = reinterpret_cast<__nv_bfloat16*>(smraw + OFF_QH);
    __nv_bfloat16* Ql = reinterpret_cast<__nv_bfloat16*>(smraw + OFF_QL);
    __nv_bfloat16* Kh = reinterpret_cast<__nv_bfloat16*>(smraw + OFF_KH);
    __nv_bfloat16* Kl = reinterpret_cast<__nv_bfloat16*>(smraw + OFF_KL);
    __nv_bfloat16* Vh = reinterpret_cast<__nv_bfloat16*>(smraw + OFF_VH);
    __nv_bfloat16* Vl = reinterpret_cast<__nv_bfloat16*>(smraw + OFF_VL);
    float* Ssm = reinterpret_cast<float*>(smraw + OFF_S);
    __nv_bfloat16* Ph = reinterpret_cast<__nv_bfloat16*>(smraw + OFF_PH);
    __nv_bfloat16* Pl = reinterpret_cast<__nv_bfloat16*>(smraw + OFF_PL);
    float* Osm = reinterpret_cast<float*>(smraw + OFF_O);

    const int tid = threadIdx.x;
    const int warp = tid >> 5;
    const int bid = blockIdx.x;
    const int qb = bid & 31;
    const int h  = (bid >> 5) & (NH - 1);
    const int b  = bid >> 9;
    const int q0 = qb * 64;
    const int sq = tid >> 3;
    const int kt = tid & 7;

    // Q tile: 64x64 bf16 hi/lo (scale pre-folded)
#pragma unroll
    for (int i = 0; i < 2; i++) {
        int f = tid + i * 256;
        int r = f >> 3;
        int seg = (f & 7) << 3;
        size_t gb = (size_t)(b * TT + q0 + r) * C3 + h * HD + seg;
        *reinterpret_cast<uint4*>(&Qh[r * AQ_STR + seg]) =
            *reinterpret_cast<const uint4*>(&qh[gb]);
        *reinterpret_cast<uint4*>(&Ql[r * AQ_STR + seg]) =
            *reinterpret_cast<const uint4*>(&ql[gb]);
    }
#pragma unroll
    for (int i = 0; i < 18; i++) {
        Osm[tid + i * 256] = 0.f;
    }

    float m1 = -1e30f;
    float l1 = 0.f;
    float m2 = -1e30f;
    float l2 = 0.f;

    const int cstart = (q0 - WINDOW > 0) ? (q0 - WINDOW) : 0;
    const int do_sink = (cstart > 0) ? 1 : 0;
    const int nwin = (q0 + 64 - cstart) / CHUNK;
    const int nch = nwin + do_sink;

    for (int phase = 0; phase < nch; phase++) {
        const int c = (do_sink && phase == 0) ? 0 : cstart + (phase - do_sink) * CHUNK;

        __syncthreads();
        // K/V chunk: 64x64 bf16 hi/lo
#pragma unroll
        for (int i = 0; i < 2; i++) {
            int f = tid + i * 256;
            int r = f >> 3;
            int seg = (f & 7) << 3;
            size_t gb = (size_t)(b * TT + c + r) * C3 + h * HD + seg;
            *reinterpret_cast<uint4*>(&Kh[r * AQ_STR + seg]) =
                *reinterpret_cast<const uint4*>(&qh[gb + CC]);
            *reinterpret_cast<uint4*>(&Kl[r * AQ_STR + seg]) =
                *reinterpret_cast<const uint4*>(&ql[gb + CC]);
            *reinterpret_cast<uint4*>(&Vh[r * AQ_STR + seg]) =
                *reinterpret_cast<const uint4*>(&qh[gb + 2 * CC]);
            *reinterpret_cast<uint4*>(&Vl[r * AQ_STR + seg]) =
                *reinterpret_cast<const uint4*>(&ql[gb + 2 * CC]);
        }
        __syncthreads();

        // ---- scores via wmma: warp covers rows (warp&3)*16, cols (warp>>2)*32 ----
        {
            const int qr = (warp & 3) * 16;
            const int kc0 = (warp >> 2) * 32;
            wmma::fragment<wmma::matrix_a, 16, 16, 16, __nv_bfloat16, wmma::row_major> fa_h[4];
            wmma::fragment<wmma::matrix_a, 16, 16, 16, __nv_bfloat16, wmma::row_major> fa_l[4];
#pragma unroll
            for (int d4 = 0; d4 < 4; d4++) {
                wmma::load_matrix_sync(fa_h[d4], &Qh[qr * AQ_STR + d4 * 16], AQ_STR);
                wmma::load_matrix_sync(fa_l[d4], &Ql[qr * AQ_STR + d4 * 16], AQ_STR);
            }
#pragma unroll
            for (int cf = 0; cf < 2; cf++) {
                const int kc = kc0 + cf * 16;
                wmma::fragment<wmma::accumulator, 16, 16, 16, float> acc_s;
                wmma::fill_fragment(acc_s, 0.0f);
#pragma unroll
                for (int d4 = 0; d4 < 4; d4++) {
                    wmma::fragment<wmma::matrix_b, 16, 16, 16, __nv_bfloat16, wmma::col_major> fb_h;
                    wmma::fragment<wmma::matrix_b, 16, 16, 16, __nv_bfloat16, wmma::col_major> fb_l;
                    wmma::load_matrix_sync(fb_h, &Kh[kc * AQ_STR + d4 * 16], AQ_STR);
                    wmma::load_matrix_sync(fb_l, &Kl[kc * AQ_STR + d4 * 16], AQ_STR);
                    wmma::mma_sync(acc_s, fa_h[d4], fb_h, acc_s);
                    wmma::mma_sync(acc_s, fa_h[d4], fb_l, acc_s);
                    wmma::mma_sync(acc_s, fa_l[d4], fb_h, acc_s);
                }
                wmma::store_matrix_sync(&Ssm[qr * AS_STR + kc], acc_s, AS_STR, wmma::mem_row_major);
            }
        }
        __syncthreads();

        // ---- scalar online softmax: 8 keys per lane per query row ----
        {
            float s1[8];
            float s2[8];
#pragma unroll
            for (int kki = 0; kki < 8; kki++) {
                s1[kki] = Ssm[sq * AS_STR + kt + kki * 8];
                s2[kki] = Ssm[(sq + 32) * AS_STR + kt + kki * 8];
            }
            const int qq1 = q0 + sq;
            const int qq2 = q0 + sq + 32;
            float mc1 = -1e30f;
            float mc2 = -1e30f;
#pragma unroll
            for (int kki = 0; kki < 8; kki++) {
                int j = c + kt + kki * 8;
                bool a1 = (j <= qq1) && (((qq1 - j) < WINDOW) || (j < SINK));
                if (!a1) s1[kki] = -1e30f;
                mc1 = fmaxf(mc1, s1[kki]);
                bool a2 = (j <= qq2) && (((qq2 - j) < WINDOW) || (j < SINK));
                if (!a2) s2[kki] = -1e30f;
                mc2 = fmaxf(mc2, s2[kki]);
            }
            mc1 = fmaxf(mc1, __shfl_xor_sync(0xffffffffu, mc1, 1));
            mc1 = fmaxf(mc1, __shfl_xor_sync(0xffffffffu, mc1, 2));
            mc1 = fmaxf(mc1, __shfl_xor_sync(0xffffffffu, mc1, 4));
            mc2 = fmaxf(mc2, __shfl_xor_sync(0xffffffffu, mc2, 1));
            mc2 = fmaxf(mc2, __shfl_xor_sync(0xffffffffu, mc2, 2));
            mc2 = fmaxf(mc2, __shfl_xor_sync(0xffffffffu, mc2, 4));
            float mn1 = fmaxf(m1, mc1);
            float mn2 = fmaxf(m2, mc2);
            float alpha1 = expf(m1 - mn1);
            float alpha2 = expf(m2 - mn2);

            float lc1 = 0.f;
            float lc2 = 0.f;
#pragma unroll
            for (int kki = 0; kki < 8; kki++) {
                int j = kt + kki * 8;
                float p1 = expf(s1[kki] - mn1);
                lc1 += p1;
                unsigned short hh;
                unsigned short ll;
                split2f(p1, hh, ll);
                Ph[sq * AP_STR + j] = __ushort_as_bfloat16(hh);
                Pl[sq * AP_STR + j] = __ushort_as_bfloat16(ll);
                float p2 = expf(s2[kki] - mn2);
                lc2 += p2;
                split2f(p2, hh, ll);
                Ph[(sq + 32) * AP_STR + j] = __ushort_as_bfloat16(hh);
                Pl[(sq + 32) * AP_STR + j] = __ushort_as_bfloat16(ll);
            }
            lc1 += __shfl_xor_sync(0xffffffffu, lc1, 1);
            lc1 += __shfl_xor_sync(0xffffffffu, lc1, 2);
            lc1 += __shfl_xor_sync(0xffffffffu, lc1, 4);
            lc2 += __shfl_xor_sync(0xffffffffu, lc2, 1);
            lc2 += __shfl_xor_sync(0xffffffffu, lc2, 2);
            lc2 += __shfl_xor_sync(0xffffffffu, lc2, 4);
            l1 = l1 * alpha1 + lc1;
            l2 = l2 * alpha2 + lc2;
            m1 = mn1;
            m2 = mn2;

#pragma unroll
            for (int e = 0; e < 4; e++) {
                Osm[sq * AO_STR + kt * 4 + e] *= alpha1;
                Osm[sq * AO_STR + kt * 4 + 32 + e] *= alpha1;
                Osm[(sq + 32) * AO_STR + kt * 4 + e] *= alpha2;
                Osm[(sq + 32) * AO_STR + kt * 4 + 32 + e] *= alpha2;
            }
        }
        __syncthreads();

        // ---- PV via wmma: warp covers rows (warp&3)*16, cols (warp>>2)*32 ----
        {
            const int qr = (warp & 3) * 16;
            const int vc0 = (warp >> 2) * 32;
            wmma::fragment<wmma::matrix_a, 16, 16, 16, __nv_bfloat16, wmma::row_major> pa_h[4];
            wmma::fragment<wmma::matrix_a, 16, 16, 16, __nv_bfloat16, wmma::row_major> pa_l[4];
#pragma unroll
            for (int k16 = 0; k16 < 4; k16++) {
                wmma::load_matrix_sync(pa_h[k16], &Ph[qr * AP_STR + k16 * 16], AP_STR);
                wmma::load_matrix_sync(pa_l[k16], &Pl[qr * AP_STR + k16 * 16], AP_STR);
            }
#pragma unroll
            for (int cf = 0; cf < 2; cf++) {
                const int vc = vc0 + cf * 16;
                wmma::fragment<wmma::accumulator, 16, 16, 16, float> acc_o;
                wmma::load_matrix_sync(acc_o, &Osm[qr * AO_STR + vc], AO_STR, wmma::mem_row_major);
#pragma unroll
                for (int k16 = 0; k16 < 4; k16++) {
                    wmma::fragment<wmma::matrix_b, 16, 16, 16, __nv_bfloat16, wmma::row_major> vb_h;
                    wmma::fragment<wmma::matrix_b, 16, 16, 16, __nv_bfloat16, wmma::row_major> vb_l;
                    wmma::load_matrix_sync(vb_h, &Vh[(k16 * 16) * AQ_STR + vc], AQ_STR);
                    wmma::load_matrix_sync(vb_l, &Vl[(k16 * 16) * AQ_STR + vc], AQ_STR);
                    wmma::mma_sync(acc_o, pa_h[k16], vb_h, acc_o);
                    wmma::mma_sync(acc_o, pa_h[k16], vb_l, acc_o);
                    wmma::mma_sync(acc_o, pa_l[k16], vb_h, acc_o);
                }
                wmma::store_matrix_sync(&Osm[qr * AO_STR + vc], acc_o, AO_STR, wmma::mem_row_major);
            }
        }
    }

    __syncthreads();

    float inv1 = 1.0f / l1;
    float inv2 = 1.0f / l2;
#pragma unroll
    for (int qi = 0; qi < 2; qi++) {
        float inv = (qi == 0) ? inv1 : inv2;
        int row = sq + qi * 32;
        size_t rowbase = (size_t)(b * TT + q0 + row) * CC + h * HD;
#pragma unroll
        for (int half = 0; half < 2; half++) {
            unsigned short hs[4];
            unsigned short ls[4];
#pragma unroll
            for (int e = 0; e < 4; e++) {
                float val = Osm[row * AO_STR + kt * 4 + half * 32 + e] * inv;
                split2f(val, hs[e], ls[e]);
            }
            uint2 hp;
            hp.x = (uint32_t)hs[0] | ((uint32_t)hs[1] << 16);
            hp.y = (uint32_t)hs[2] | ((uint32_t)hs[3] << 16);
            uint2 lp;
            lp.x = (uint32_t)ls[0] | ((uint32_t)ls[1] << 16);
            lp.y = (uint32_t)ls[2] | ((uint32_t)ls[3] << 16);
            size_t off = rowbase + kt * 4 + half * 32;
            *reinterpret_cast<uint2*>(&ath[off]) = hp;
            *reinterpret_cast<uint2*>(&atl[off]) = lp;
        }
    }
}

// ---------------------------------------------------------------------------
extern "C" void kernel_launch(void* const* d_in, const int* in_sizes, int n_in,
                              void* d_out, int out_size)
{
    const float* x = nullptr;
    const float* w_attn = nullptr;
    const float* w_proj = nullptr;
    for (int i = 0; i < n_in; i++) {
        if (in_sizes[i] == BB * TT * CC)      x      = (const float*)d_in[i];
        else if (in_sizes[i] == CC * C3)      w_attn = (const float*)d_in[i];
        else if (in_sizes[i] == CC * CC)      w_proj = (const float*)d_in[i];
    }
    if (!x || !w_attn || !w_proj) {
        x      = (const float*)d_in[0];
        w_attn = (const float*)d_in[1];
        w_proj = (const float*)d_in[2];
    }
    float* out = (float*)d_out;

    void* p;
    cudaGetSymbolAddress(&p, g_qkv);
    float* qkv = (float*)p;
    cudaGetSymbolAddress(&p, g_qkvh);
    __nv_bfloat16* qkvh = (__nv_bfloat16*)p;
    cudaGetSymbolAddress(&p, g_qkvl);
    __nv_bfloat16* qkvl = (__nv_bfloat16*)p;
    cudaGetSymbolAddress(&p, g_xh);
    __nv_bfloat16* xh = (__nv_bfloat16*)p;
    cudaGetSymbolAddress(&p, g_xl);
    __nv_bfloat16* xl = (__nv_bfloat16*)p;
    cudaGetSymbolAddress(&p, g_wah);
    __nv_bfloat16* wah = (__nv_bfloat16*)p;
    cudaGetSymbolAddress(&p, g_wal);
    __nv_bfloat16* wal = (__nv_bfloat16*)p;
    cudaGetSymbolAddress(&p, g_wph);
    __nv_bfloat16* wph = (__nv_bfloat16*)p;
    cudaGetSymbolAddress(&p, g_wpl);
    __nv_bfloat16* wpl = (__nv_bfloat16*)p;
    cudaGetSymbolAddress(&p, g_ath);
    __nv_bfloat16* ath = (__nv_bfloat16*)p;
    cudaGetSymbolAddress(&p, g_atl);
    __nv_bfloat16* atl = (__nv_bfloat16*)p;

    cudaFuncSetAttribute(gemm_tc_kernel,
                         cudaFuncAttributeMaxDynamicSharedMemorySize,
                         GEMM_SMEM_BYTES);
    cudaFuncSetAttribute(attn_kernel,
                         cudaFuncAttributeMaxDynamicSharedMemorySize,
                         ATTN_SMEM_BYTES);

    {
        int n4 = (MROWS * CC) / 4;
        split_kernel<<<(n4 + 255) / 256, 256>>>(x, xh, xl, n4);
    }
    {
        int n4 = (CC * C3) / 4;
        split_kernel<<<(n4 + 255) / 256, 256>>>(w_attn, wah, wal, n4);
    }
    {
        int n4 = (CC * CC) / 4;
        split_kernel<<<(n4 + 255) / 256, 256>>>(w_proj, wph, wpl, n4);
    }
    {
        dim3 grid(C3 / 128, MROWS / 128);
        gemm_tc_kernel<<<grid, 256, GEMM_SMEM_BYTES>>>(xh, xl, wah, wal, qkv, MROWS, C3, CC);
    }
    {
        int total = BB * TT * NH * 32;
        rope_split_kernel<<<total / 256, 256>>>(qkv, qkvh, qkvl);
    }
    {
        int grid = BB * NH * (TT / 64);
        attn_kernel<<<grid, 256, ATTN_SMEM_BYTES>>>(qkvh, qkvl, ath, atl);
    }
    {
        dim3 grid(CC / 128, MROWS / 128);
        gemm_tc_kernel<<<grid, 256, GEMM_SMEM_BYTES>>>(ath, atl, wph, wpl, out, MROWS, CC, CC);
    }
}